// round 5
// baseline (speedup 1.0000x reference)
#include <cuda_runtime.h>
#include <cuda_bf16.h>
#include <math.h>

#define NN   100000
#define M3   3
#define DIN  128
#define DH   64
#define NE   1600000
#define NP   ((long long)M3 * NN)       // 300000 rows

// ---- scratch (static device allocations; no cudaMalloc allowed) ----
__device__ float g_proj[(size_t)M3 * NN * DH];   // [m][n][h]
__device__ float g_h   [(size_t)M3 * NN * DH];   // agg, then post-prelu h
__device__ float g_deg [(size_t)M3 * NN];
__device__ float g_logits[M3];
__device__ float g_beta[M3];

__device__ __forceinline__ float tanh_fast(float x) {
    float y;
    asm("tanh.approx.f32 %0, %1;" : "=f"(y) : "f"(x));
    return y;
}

// ---------------------------------------------------------------------------
// Kernel 0: zero agg/deg/logits
// ---------------------------------------------------------------------------
__global__ void zero_kernel() {
    size_t i = (size_t)blockIdx.x * blockDim.x + threadIdx.x;
    size_t tot4 = (size_t)M3 * NN * DH / 4;           // 4.8M float4
    if (i < tot4) ((float4*)g_h)[i] = make_float4(0.f, 0.f, 0.f, 0.f);
    if (i < (size_t)M3 * NN / 4) ((float4*)g_deg)[i] = make_float4(0.f, 0.f, 0.f, 0.f);
    if (i == 0) { g_logits[0] = 0.f; g_logits[1] = 0.f; g_logits[2] = 0.f; }
}

// ---------------------------------------------------------------------------
// Kernel 1: proj[m][n][h] = sum_d feats[m][n][d] * W[m][d][h]
// 64x64 tile, 256 threads, 4x4 microtile, A-tile transposed (stride 68).
// ---------------------------------------------------------------------------
__global__ __launch_bounds__(256) void proj_kernel(const float* __restrict__ feats,
                                                   const float* __restrict__ W) {
    __shared__ __align__(16) float sFT[64][68];  // [k][node], 16B-aligned float4 slots
    __shared__ __align__(16) float sW[64][DH];   // [k][h]
    const int m  = blockIdx.y;
    const int n0 = blockIdx.x * 64;
    const int tid = threadIdx.x;
    const int tx = tid & 15, ty = tid >> 4;

    const float* fbase = feats + (size_t)m * NN * DIN;
    const float* wbase = W + (size_t)m * DIN * DH;

    float acc[4][4] = {};
    for (int kk = 0; kk < DIN; kk += 64) {
        for (int i = tid; i < 64 * 64; i += 256) {
            int r = i >> 6, c = i & 63;
            int n = n0 + r;
            sFT[c][r] = (n < NN) ? fbase[(size_t)n * DIN + kk + c] : 0.f;
        }
        for (int i = tid; i < 64 * DH; i += 256) {
            int r = i >> 6, c = i & 63;
            sW[r][c] = wbase[(size_t)(kk + r) * DH + c];
        }
        __syncthreads();
#pragma unroll
        for (int k = 0; k < 64; k++) {
            float4 av = *(const float4*)&sFT[k][ty * 4];
            float4 bv = *(const float4*)&sW[k][tx * 4];
            acc[0][0] += av.x * bv.x; acc[0][1] += av.x * bv.y; acc[0][2] += av.x * bv.z; acc[0][3] += av.x * bv.w;
            acc[1][0] += av.y * bv.x; acc[1][1] += av.y * bv.y; acc[1][2] += av.y * bv.z; acc[1][3] += av.y * bv.w;
            acc[2][0] += av.z * bv.x; acc[2][1] += av.z * bv.y; acc[2][2] += av.z * bv.z; acc[2][3] += av.z * bv.w;
            acc[3][0] += av.w * bv.x; acc[3][1] += av.w * bv.y; acc[3][2] += av.w * bv.z; acc[3][3] += av.w * bv.w;
        }
        __syncthreads();
    }
#pragma unroll
    for (int i = 0; i < 4; i++) {
        int n = n0 + ty * 4 + i;
        if (n < NN) {
            float4 v = make_float4(acc[i][0], acc[i][1], acc[i][2], acc[i][3]);
            *(float4*)&g_proj[((size_t)m * NN + n) * DH + tx * 4] = v;
        }
    }
}

// ---------------------------------------------------------------------------
// Kernel 2: scatter edges: g_h[m][dst] += g_proj[m][src]; degree count.
// ---------------------------------------------------------------------------
__global__ __launch_bounds__(256) void scatter_kernel(const int* __restrict__ src,
                                                      const int* __restrict__ dst) {
    long long gid = (long long)blockIdx.x * blockDim.x + threadIdx.x;
    long long e = gid >> 4;
    if (e >= (long long)M3 * NE) return;
    int part = (int)(gid & 15);
    int m  = (int)(e / NE);
    int ei = (int)(e - (long long)m * NE);
    int s = src[(size_t)m * NE + ei];
    int d = dst[(size_t)m * NE + ei];
    float4 v = *(const float4*)(g_proj + ((size_t)m * NN + s) * DH + part * 4);
    float* p = g_h + ((size_t)m * NN + d) * DH + part * 4;
    asm volatile("red.global.add.v4.f32 [%0], {%1,%2,%3,%4};"
                 :: "l"(p), "f"(v.x), "f"(v.y), "f"(v.z), "f"(v.w) : "memory");
    if (part == 0) atomicAdd(&g_deg[(size_t)m * NN + d], 1.0f);
}

// ---------------------------------------------------------------------------
// Kernel 3: finalize as GEMM. Rows p = m*NN+n (300000), tile 64 rows/block.
// Prologue: h = prelu(agg/deg + b) (written back to g_h + staged transposed).
// Mainloop: C[64x64] = A[64x64] @ fcW[64x64], acc init = fc_b.
// Epilogue: s = tanh(C); logits[m] += sum_rows dot(s_row, attn).
// ---------------------------------------------------------------------------
__global__ __launch_bounds__(256) void finalize_gemm(const float* __restrict__ b,
                                                     const float* __restrict__ prelu_a,
                                                     const float* __restrict__ fc_W,
                                                     const float* __restrict__ fc_b,
                                                     const float* __restrict__ attn) {
    __shared__ __align__(16) float sAT[64][68];   // [k][row]
    __shared__ __align__(16) float sW[64][DH];    // [k][col]
    __shared__ float sInv[64];
    __shared__ float sLog[2];
    const int tid = threadIdx.x;
    const int tx = tid & 15, ty = tid >> 4;
    const long long p0 = (long long)blockIdx.x * 64;
    const int m0 = (int)(p0 / NN);

    // weights
    for (int i = tid; i < 64 * DH; i += 256) sW[i >> 6][i & 63] = fc_W[i];
    if (tid < 64) {
        long long p = p0 + tid;
        sInv[tid] = (p < NP) ? (1.0f / fmaxf(g_deg[p], 1.0f)) : 0.f;
    }
    if (tid < 2) sLog[tid] = 0.f;
    __syncthreads();

    const float a0p = prelu_a[0], a1p = prelu_a[1], a2p = prelu_a[2];

    // A tile: compute h, write back, stage transposed
    for (int i = tid; i < 64 * 64; i += 256) {
        int r = i >> 6, k = i & 63;
        long long p = p0 + r;
        float v = 0.f;
        if (p < NP) {
            int m = (int)(p / NN);
            float a = (m == 0) ? a0p : (m == 1) ? a1p : a2p;
            v = g_h[(size_t)p * DH + k] * sInv[r] + b[m * DH + k];
            v = (v > 0.f) ? v : a * v;
            g_h[(size_t)p * DH + k] = v;
        }
        sAT[k][r] = v;
    }
    __syncthreads();

    const float4 fcb4 = *(const float4*)&fc_b[tx * 4];
    float acc[4][4];
#pragma unroll
    for (int i = 0; i < 4; i++) { acc[i][0] = fcb4.x; acc[i][1] = fcb4.y; acc[i][2] = fcb4.z; acc[i][3] = fcb4.w; }

#pragma unroll
    for (int k = 0; k < 64; k++) {
        float4 av = *(const float4*)&sAT[k][ty * 4];
        float4 bv = *(const float4*)&sW[k][tx * 4];
        acc[0][0] += av.x * bv.x; acc[0][1] += av.x * bv.y; acc[0][2] += av.x * bv.z; acc[0][3] += av.x * bv.w;
        acc[1][0] += av.y * bv.x; acc[1][1] += av.y * bv.y; acc[1][2] += av.y * bv.z; acc[1][3] += av.y * bv.w;
        acc[2][0] += av.z * bv.x; acc[2][1] += av.z * bv.y; acc[2][2] += av.z * bv.z; acc[2][3] += av.z * bv.w;
        acc[3][0] += av.w * bv.x; acc[3][1] += av.w * bv.y; acc[3][2] += av.w * bv.z; acc[3][3] += av.w * bv.w;
    }

    // epilogue: tanh, dot with attn, reduce
    const float4 at4 = *(const float4*)&attn[tx * 4];
    float sum0 = 0.f, sum1 = 0.f;
#pragma unroll
    for (int i = 0; i < 4; i++) {
        long long p = p0 + ty * 4 + i;
        float v = tanh_fast(acc[i][0]) * at4.x + tanh_fast(acc[i][1]) * at4.y
                + tanh_fast(acc[i][2]) * at4.z + tanh_fast(acc[i][3]) * at4.w;
        if (p >= NP) v = 0.f;
        // reduce across the 16 tx lanes (offsets stay within 16-lane half)
#pragma unroll
        for (int o = 8; o; o >>= 1) v += __shfl_xor_sync(0xffffffffu, v, o);
        if (tx == 0) {
            int m = (int)(p / NN);
            if (m == m0) sum0 += v; else sum1 += v;
        }
    }
    if (tx == 0) {
        if (sum0 != 0.f) atomicAdd(&sLog[0], sum0);
        if (sum1 != 0.f) atomicAdd(&sLog[1], sum1);
    }
    __syncthreads();
    if (tid == 0) {
        if (sLog[0] != 0.f) atomicAdd(&g_logits[m0], sLog[0]);
        if (m0 + 1 < M3 && sLog[1] != 0.f) atomicAdd(&g_logits[m0 + 1], sLog[1]);
    }
}

// ---------------------------------------------------------------------------
// Kernel 4: beta = softmax(logits / N)
// ---------------------------------------------------------------------------
__global__ void beta_kernel() {
    if (threadIdx.x == 0) {
        float l0 = g_logits[0] / (float)NN;
        float l1 = g_logits[1] / (float)NN;
        float l2 = g_logits[2] / (float)NN;
        float mx = fmaxf(l0, fmaxf(l1, l2));
        float e0 = expf(l0 - mx), e1 = expf(l1 - mx), e2 = expf(l2 - mx);
        float s = e0 + e1 + e2;
        g_beta[0] = e0 / s; g_beta[1] = e1 / s; g_beta[2] = e2 / s;
    }
}

// ---------------------------------------------------------------------------
// Kernel 5: z[n][h] = sum_m beta[m] * h[m][n][h]
// ---------------------------------------------------------------------------
__global__ __launch_bounds__(256) void z_kernel(float* __restrict__ out) {
    size_t i = (size_t)blockIdx.x * blockDim.x + threadIdx.x;
    size_t tot = (size_t)NN * DH / 4;
    if (i >= tot) return;
    float b0 = g_beta[0], b1 = g_beta[1], b2 = g_beta[2];
    float4 h0 = ((const float4*)(g_h + (size_t)0 * NN * DH))[i];
    float4 h1 = ((const float4*)(g_h + (size_t)1 * NN * DH))[i];
    float4 h2 = ((const float4*)(g_h + (size_t)2 * NN * DH))[i];
    float4 r;
    r.x = b0 * h0.x + b1 * h1.x + b2 * h2.x;
    r.y = b0 * h0.y + b1 * h1.y + b2 * h2.y;
    r.z = b0 * h0.z + b1 * h1.z + b2 * h2.z;
    r.w = b0 * h0.w + b1 * h1.w + b2 * h2.w;
    ((float4*)out)[i] = r;
}

// ---------------------------------------------------------------------------
extern "C" void kernel_launch(void* const* d_in, const int* in_sizes, int n_in,
                              void* d_out, int out_size) {
    const float* feats   = (const float*)d_in[0];
    const int*   src     = (const int*)  d_in[1];
    const int*   dst     = (const int*)  d_in[2];
    const float* W       = (const float*)d_in[3];
    const float* b       = (const float*)d_in[4];
    const float* prelu_a = (const float*)d_in[5];
    const float* fc_W    = (const float*)d_in[6];
    const float* fc_b    = (const float*)d_in[7];
    const float* attn    = (const float*)d_in[8];
    float* out = (float*)d_out;

    // 0) zero scratch
    {
        size_t tot4 = (size_t)M3 * NN * DH / 4;
        int grid = (int)((tot4 + 255) / 256);
        zero_kernel<<<grid, 256>>>();
    }
    // 1) proj GEMM
    {
        dim3 grid((NN + 63) / 64, M3);
        proj_kernel<<<grid, 256>>>(feats, W);
    }
    // 2) scatter + degree
    {
        long long threads = (long long)M3 * NE * 16;
        int grid = (int)((threads + 255) / 256);
        scatter_kernel<<<grid, 256>>>(src, dst);
    }
    // 3) finalize GEMM (h, tanh matvec, logits)
    {
        int grid = (int)((NP + 63) / 64);   // 4688
        finalize_gemm<<<grid, 256>>>(b, prelu_a, fc_W, fc_b, attn);
    }
    // 4) beta
    beta_kernel<<<1, 32>>>();
    // 5) z
    {
        size_t tot = (size_t)NN * DH / 4;
        int grid = (int)((tot + 255) / 256);
        z_kernel<<<grid, 256>>>(out);
    }
}

// round 6
// speedup vs baseline: 1.3698x; 1.3698x over previous
#include <cuda_runtime.h>
#include <cuda_bf16.h>
#include <math.h>

#define NN   100000
#define M3   3
#define DIN  128
#define DH   64
#define NE   1600000
#define NP   300000                     // M3*NN rows
#define NET  4800000                    // M3*NE edges
#define SCAN_CHUNK 2048
#define SCAN_NBLK  147                  // ceil(NP/2048)

// ---- scratch (static device allocations; no cudaMalloc allowed) ----
__device__ float g_proj[(size_t)NP * DH];        // [p][h]
__device__ float g_h   [(size_t)NP * DH];        // post-prelu h
__device__ int   g_cnt [NP];                     // per-node in-degree
__device__ int   g_rowStart[NP];                 // CSR row starts (exclusive scan)
__device__ int   g_cursor[NP];                   // fill cursors
__device__ int   g_eidx[NET];                    // bucketed source row ids (m*NN+src)
__device__ int   g_blockSums[SCAN_NBLK];
__device__ int   g_blockOff [SCAN_NBLK];
__device__ float g_logits[M3];
__device__ float g_beta[M3];

__device__ __forceinline__ float tanh_fast(float x) {
    float y;
    asm("tanh.approx.f32 %0, %1;" : "=f"(y) : "f"(x));
    return y;
}

// ---------------------------------------------------------------------------
// Kernel 0: zero counters + logits
// ---------------------------------------------------------------------------
__global__ void zero_kernel() {
    int i = blockIdx.x * blockDim.x + threadIdx.x;
    if (i < NP) g_cnt[i] = 0;
    if (i < M3) g_logits[i] = 0.f;
}

// ---------------------------------------------------------------------------
// Kernel 1: proj[p][h] = sum_d feats[m][n][d] * W[m][d][h]   (unchanged)
// ---------------------------------------------------------------------------
__global__ __launch_bounds__(256) void proj_kernel(const float* __restrict__ feats,
                                                   const float* __restrict__ W) {
    __shared__ __align__(16) float sFT[64][68];
    __shared__ __align__(16) float sW[64][DH];
    const int m  = blockIdx.y;
    const int n0 = blockIdx.x * 64;
    const int tid = threadIdx.x;
    const int tx = tid & 15, ty = tid >> 4;

    const float* fbase = feats + (size_t)m * NN * DIN;
    const float* wbase = W + (size_t)m * DIN * DH;

    float acc[4][4] = {};
    for (int kk = 0; kk < DIN; kk += 64) {
        for (int i = tid; i < 64 * 64; i += 256) {
            int r = i >> 6, c = i & 63;
            int n = n0 + r;
            sFT[c][r] = (n < NN) ? fbase[(size_t)n * DIN + kk + c] : 0.f;
        }
        for (int i = tid; i < 64 * DH; i += 256) {
            int r = i >> 6, c = i & 63;
            sW[r][c] = wbase[(size_t)(kk + r) * DH + c];
        }
        __syncthreads();
#pragma unroll
        for (int k = 0; k < 64; k++) {
            float4 av = *(const float4*)&sFT[k][ty * 4];
            float4 bv = *(const float4*)&sW[k][tx * 4];
            acc[0][0] += av.x * bv.x; acc[0][1] += av.x * bv.y; acc[0][2] += av.x * bv.z; acc[0][3] += av.x * bv.w;
            acc[1][0] += av.y * bv.x; acc[1][1] += av.y * bv.y; acc[1][2] += av.y * bv.z; acc[1][3] += av.y * bv.w;
            acc[2][0] += av.z * bv.x; acc[2][1] += av.z * bv.y; acc[2][2] += av.z * bv.z; acc[2][3] += av.z * bv.w;
            acc[3][0] += av.w * bv.x; acc[3][1] += av.w * bv.y; acc[3][2] += av.w * bv.z; acc[3][3] += av.w * bv.w;
        }
        __syncthreads();
    }
#pragma unroll
    for (int i = 0; i < 4; i++) {
        int n = n0 + ty * 4 + i;
        if (n < NN) {
            float4 v = make_float4(acc[i][0], acc[i][1], acc[i][2], acc[i][3]);
            *(float4*)&g_proj[((size_t)m * NN + n) * DH + tx * 4] = v;
        }
    }
}

// ---------------------------------------------------------------------------
// Kernel 2a: histogram of dst
// ---------------------------------------------------------------------------
__global__ __launch_bounds__(256) void hist_kernel(const int* __restrict__ dst) {
    int gid = blockIdx.x * blockDim.x + threadIdx.x;
    if (gid >= NET) return;
    int m = gid / NE;
    atomicAdd(&g_cnt[m * NN + dst[gid]], 1);
}

// ---------------------------------------------------------------------------
// Kernel 2b: per-chunk sums (chunk = 2048, thread handles 8 consecutive)
// ---------------------------------------------------------------------------
__global__ __launch_bounds__(256) void scan1_kernel() {
    __shared__ int s[256];
    int tid = threadIdx.x;
    int base = blockIdx.x * SCAN_CHUNK + tid * 8;
    int sum = 0;
#pragma unroll
    for (int j = 0; j < 8; j++) {
        int i = base + j;
        if (i < NP) sum += g_cnt[i];
    }
    s[tid] = sum; __syncthreads();
    for (int off = 128; off; off >>= 1) {
        if (tid < off) s[tid] += s[tid + off];
        __syncthreads();
    }
    if (tid == 0) g_blockSums[blockIdx.x] = s[0];
}

// ---------------------------------------------------------------------------
// Kernel 2c: exclusive scan of chunk sums (serial, 147 elems)
// ---------------------------------------------------------------------------
__global__ void scan2_kernel() {
    if (threadIdx.x == 0) {
        int run = 0;
        for (int i = 0; i < SCAN_NBLK; i++) { g_blockOff[i] = run; run += g_blockSums[i]; }
    }
}

// ---------------------------------------------------------------------------
// Kernel 2d: per-chunk exclusive scan + offset -> rowStart, cursor
// ---------------------------------------------------------------------------
__global__ __launch_bounds__(256) void scan3_kernel() {
    __shared__ int s[256];
    int tid = threadIdx.x;
    int base = blockIdx.x * SCAN_CHUNK + tid * 8;
    int cnt8[8];
    int sum = 0;
#pragma unroll
    for (int j = 0; j < 8; j++) {
        int i = base + j;
        cnt8[j] = (i < NP) ? g_cnt[i] : 0;
        sum += cnt8[j];
    }
    s[tid] = sum; __syncthreads();
    // Hillis-Steele inclusive scan of thread sums
    for (int off = 1; off < 256; off <<= 1) {
        int add = (tid >= off) ? s[tid - off] : 0;
        __syncthreads();
        s[tid] += add;
        __syncthreads();
    }
    int run = g_blockOff[blockIdx.x] + s[tid] - sum;   // exclusive prefix for this thread
#pragma unroll
    for (int j = 0; j < 8; j++) {
        int i = base + j;
        if (i < NP) { g_rowStart[i] = run; g_cursor[i] = run; }
        run += cnt8[j];
    }
}

// ---------------------------------------------------------------------------
// Kernel 2e: fill buckets: eidx[pos] = m*NN+src
// ---------------------------------------------------------------------------
__global__ __launch_bounds__(256) void fill_kernel(const int* __restrict__ src,
                                                   const int* __restrict__ dst) {
    int gid = blockIdx.x * blockDim.x + threadIdx.x;
    if (gid >= NET) return;
    int m = gid / NE;
    int pos = atomicAdd(&g_cursor[m * NN + dst[gid]], 1);
    g_eidx[pos] = m * NN + src[gid];
}

// ---------------------------------------------------------------------------
// Kernel 2f: pull-aggregate + finish h: 16 threads per node.
// h[p] = prelu( (sum_{e in row(p)} proj[eidx[e]]) / max(deg,1) + b[m] )
// ---------------------------------------------------------------------------
__global__ __launch_bounds__(256) void aggregate_kernel(const float* __restrict__ b,
                                                        const float* __restrict__ prelu_a) {
    long long gid = (long long)blockIdx.x * blockDim.x + threadIdx.x;
    long long node16 = gid >> 4;
    if (node16 >= NP) return;
    int p = (int)node16;
    int part = (int)(gid & 15);
    int rs = g_rowStart[p];
    int c  = g_cnt[p];
    const float4* proj4 = (const float4*)g_proj;

    float4 a0 = make_float4(0.f, 0.f, 0.f, 0.f);
    float4 a1 = make_float4(0.f, 0.f, 0.f, 0.f);
    int e = rs, re = rs + c;
    for (; e + 1 < re; e += 2) {
        int i0 = g_eidx[e], i1 = g_eidx[e + 1];
        float4 v0 = proj4[(size_t)i0 * 16 + part];
        float4 v1 = proj4[(size_t)i1 * 16 + part];
        a0.x += v0.x; a0.y += v0.y; a0.z += v0.z; a0.w += v0.w;
        a1.x += v1.x; a1.y += v1.y; a1.z += v1.z; a1.w += v1.w;
    }
    if (e < re) {
        int i0 = g_eidx[e];
        float4 v0 = proj4[(size_t)i0 * 16 + part];
        a0.x += v0.x; a0.y += v0.y; a0.z += v0.z; a0.w += v0.w;
    }
    int m = p / NN;
    float inv = 1.0f / (float)max(c, 1);
    float4 bb = *(const float4*)&b[m * DH + part * 4];
    float a = prelu_a[m];
    float4 h;
    h.x = a0.x + a1.x; h.y = a0.y + a1.y; h.z = a0.z + a1.z; h.w = a0.w + a1.w;
    h.x = h.x * inv + bb.x; h.y = h.y * inv + bb.y; h.z = h.z * inv + bb.z; h.w = h.w * inv + bb.w;
    h.x = (h.x > 0.f) ? h.x : a * h.x;
    h.y = (h.y > 0.f) ? h.y : a * h.y;
    h.z = (h.z > 0.f) ? h.z : a * h.z;
    h.w = (h.w > 0.f) ? h.w : a * h.w;
    *(float4*)&g_h[(size_t)p * DH + part * 4] = h;
}

// ---------------------------------------------------------------------------
// Kernel 3: finalize (R2-v2 shape, simplified): s = tanh(h@fcW + fcb);
// logits[m] += dot(s, attn). 4 nodes per warp per iter.
// ---------------------------------------------------------------------------
__global__ __launch_bounds__(256) void finalize_kernel(const float* __restrict__ fc_W,
                                                       const float* __restrict__ fc_b,
                                                       const float* __restrict__ attn) {
    __shared__ __align__(16) float4 sW4[DH / 2][32];
    __shared__ __align__(16) float  sh[8][4][DH];
    __shared__ float sLog[M3];
    const int tid = threadIdx.x;
    const int wid = tid >> 5, lane = tid & 31;

    for (int i = tid; i < (DH / 2) * 32; i += 256) {
        int kk = i >> 5, c = i & 31;
        int k = kk * 2;
        sW4[kk][c] = make_float4(fc_W[k * DH + c],       fc_W[k * DH + c + 32],
                                 fc_W[(k + 1) * DH + c], fc_W[(k + 1) * DH + c + 32]);
    }
    if (tid < M3) sLog[tid] = 0.f;
    __syncthreads();

    const float fcb0 = fc_b[lane],      fcb1 = fc_b[lane + 32];
    const float at0  = attn[lane],      at1  = attn[lane + 32];

    const long long totalGroups = (long long)NP / 4;   // 75000
    const int totalWarps = gridDim.x * (blockDim.x >> 5);
    float log0 = 0.f, log1 = 0.f, log2 = 0.f;

    for (long long g = (long long)blockIdx.x * (blockDim.x >> 5) + wid;
         g < totalGroups; g += totalWarps) {
        long long p0 = g * 4;
        const int m = (int)(p0 / NN);          // 4 | NN, group never crosses m
        float acc0[4], acc1[4];
#pragma unroll
        for (int j = 0; j < 4; j++) {
            size_t base = (size_t)(p0 + j) * DH;
            float h0 = g_h[base + lane];
            float h1 = g_h[base + lane + 32];
            sh[wid][j][lane]      = h0;
            sh[wid][j][lane + 32] = h1;
            acc0[j] = fcb0; acc1[j] = fcb1;
        }
        __syncwarp();
#pragma unroll
        for (int kk = 0; kk < DH / 2; kk++) {
            float4 w = sW4[kk][lane];
#pragma unroll
            for (int j = 0; j < 4; j++) {
                float2 hk = *(const float2*)&sh[wid][j][kk * 2];  // broadcast
                acc0[j] += hk.x * w.x + hk.y * w.z;
                acc1[j] += hk.x * w.y + hk.y * w.w;
            }
        }
        float lsum = 0.f;
#pragma unroll
        for (int j = 0; j < 4; j++) {
            float part = tanh_fast(acc0[j]) * at0 + tanh_fast(acc1[j]) * at1;
#pragma unroll
            for (int o = 16; o; o >>= 1) part += __shfl_down_sync(0xffffffffu, part, o);
            lsum += part;
        }
        if (lane == 0) {
            if (m == 0)      log0 += lsum;
            else if (m == 1) log1 += lsum;
            else             log2 += lsum;
        }
        __syncwarp();
    }
    if (lane == 0) {
        if (log0 != 0.f) atomicAdd(&sLog[0], log0);
        if (log1 != 0.f) atomicAdd(&sLog[1], log1);
        if (log2 != 0.f) atomicAdd(&sLog[2], log2);
    }
    __syncthreads();
    if (tid < M3) atomicAdd(&g_logits[tid], sLog[tid]);
}

// ---------------------------------------------------------------------------
// Kernel 4: beta = softmax(logits / N)
// ---------------------------------------------------------------------------
__global__ void beta_kernel() {
    if (threadIdx.x == 0) {
        float l0 = g_logits[0] / (float)NN;
        float l1 = g_logits[1] / (float)NN;
        float l2 = g_logits[2] / (float)NN;
        float mx = fmaxf(l0, fmaxf(l1, l2));
        float e0 = expf(l0 - mx), e1 = expf(l1 - mx), e2 = expf(l2 - mx);
        float s = e0 + e1 + e2;
        g_beta[0] = e0 / s; g_beta[1] = e1 / s; g_beta[2] = e2 / s;
    }
}

// ---------------------------------------------------------------------------
// Kernel 5: z[n][h] = sum_m beta[m] * h[m][n][h]
// ---------------------------------------------------------------------------
__global__ __launch_bounds__(256) void z_kernel(float* __restrict__ out) {
    size_t i = (size_t)blockIdx.x * blockDim.x + threadIdx.x;
    size_t tot = (size_t)NN * DH / 4;
    if (i >= tot) return;
    float b0 = g_beta[0], b1 = g_beta[1], b2 = g_beta[2];
    float4 h0 = ((const float4*)(g_h + (size_t)0 * NN * DH))[i];
    float4 h1 = ((const float4*)(g_h + (size_t)1 * NN * DH))[i];
    float4 h2 = ((const float4*)(g_h + (size_t)2 * NN * DH))[i];
    float4 r;
    r.x = b0 * h0.x + b1 * h1.x + b2 * h2.x;
    r.y = b0 * h0.y + b1 * h1.y + b2 * h2.y;
    r.z = b0 * h0.z + b1 * h1.z + b2 * h2.z;
    r.w = b0 * h0.w + b1 * h1.w + b2 * h2.w;
    ((float4*)out)[i] = r;
}

// ---------------------------------------------------------------------------
extern "C" void kernel_launch(void* const* d_in, const int* in_sizes, int n_in,
                              void* d_out, int out_size) {
    const float* feats   = (const float*)d_in[0];
    const int*   src     = (const int*)  d_in[1];
    const int*   dst     = (const int*)  d_in[2];
    const float* W       = (const float*)d_in[3];
    const float* b       = (const float*)d_in[4];
    const float* prelu_a = (const float*)d_in[5];
    const float* fc_W    = (const float*)d_in[6];
    const float* fc_b    = (const float*)d_in[7];
    const float* attn    = (const float*)d_in[8];
    float* out = (float*)d_out;

    zero_kernel<<<(NP + 255) / 256, 256>>>();
    {
        dim3 grid((NN + 63) / 64, M3);
        proj_kernel<<<grid, 256>>>(feats, W);
    }
    hist_kernel<<<(NET + 255) / 256, 256>>>(dst);
    scan1_kernel<<<SCAN_NBLK, 256>>>();
    scan2_kernel<<<1, 32>>>();
    scan3_kernel<<<SCAN_NBLK, 256>>>();
    fill_kernel<<<(NET + 255) / 256, 256>>>(src, dst);
    {
        long long threads = (long long)NP * 16;
        aggregate_kernel<<<(int)((threads + 255) / 256), 256>>>(b, prelu_a);
    }
    finalize_kernel<<<2048, 256>>>(fc_W, fc_b, attn);
    beta_kernel<<<1, 32>>>();
    {
        size_t tot = (size_t)NN * DH / 4;
        z_kernel<<<(int)((tot + 255) / 256), 256>>>(out);
    }
}

// round 8
// speedup vs baseline: 1.4115x; 1.0304x over previous
#include <cuda_runtime.h>
#include <cuda_fp16.h>
#include <math.h>

#define NN   100000
#define M3   3
#define DIN  128
#define DH   64
#define NE   1600000
#define NP   300000                     // M3*NN rows
#define NET  4800000                    // M3*NE edges
#define SCAN_CHUNK 2048
#define SCAN_NBLK  147                  // ceil(NP/2048)

// ---- scratch (static device allocations; no cudaMalloc allowed) ----
__device__ __half g_projh[(size_t)NP * DH];      // [p][h] fp16 (gather-bandwidth lever)
__device__ float g_h   [(size_t)NP * DH];        // post-prelu h
__device__ int   g_cnt [NP];                     // per-node in-degree
__device__ int   g_rowStart[NP];                 // CSR row starts
__device__ int   g_cursor[NP];                   // fill cursors
__device__ int   g_eidx[NET];                    // bucketed source row ids (m*NN+src)
__device__ int   g_blockSums[SCAN_NBLK];
__device__ int   g_blockOff [SCAN_NBLK];
__device__ float g_logits[M3];
__device__ float g_beta[M3];

__device__ __forceinline__ float tanh_fast(float x) {
    float y;
    asm("tanh.approx.f32 %0, %1;" : "=f"(y) : "f"(x));
    return y;
}

// ---------------------------------------------------------------------------
// Kernel 0: zero counters + logits
// ---------------------------------------------------------------------------
__global__ void zero_kernel() {
    int i = blockIdx.x * blockDim.x + threadIdx.x;
    if (i < NP) g_cnt[i] = 0;
    if (i < M3) g_logits[i] = 0.f;
}

// ---------------------------------------------------------------------------
// Kernel 1: proj (fp32 GEMM, fp16 output)
// ---------------------------------------------------------------------------
__global__ __launch_bounds__(256) void proj_kernel(const float* __restrict__ feats,
                                                   const float* __restrict__ W) {
    __shared__ __align__(16) float sFT[64][68];
    __shared__ __align__(16) float sW[64][DH];
    const int m  = blockIdx.y;
    const int n0 = blockIdx.x * 64;
    const int tid = threadIdx.x;
    const int tx = tid & 15, ty = tid >> 4;

    const float* fbase = feats + (size_t)m * NN * DIN;
    const float* wbase = W + (size_t)m * DIN * DH;

    float acc[4][4] = {};
    for (int kk = 0; kk < DIN; kk += 64) {
        for (int i = tid; i < 64 * 64; i += 256) {
            int r = i >> 6, c = i & 63;
            int n = n0 + r;
            sFT[c][r] = (n < NN) ? fbase[(size_t)n * DIN + kk + c] : 0.f;
        }
        for (int i = tid; i < 64 * DH; i += 256) {
            int r = i >> 6, c = i & 63;
            sW[r][c] = wbase[(size_t)(kk + r) * DH + c];
        }
        __syncthreads();
#pragma unroll
        for (int k = 0; k < 64; k++) {
            float4 av = *(const float4*)&sFT[k][ty * 4];
            float4 bv = *(const float4*)&sW[k][tx * 4];
            acc[0][0] += av.x * bv.x; acc[0][1] += av.x * bv.y; acc[0][2] += av.x * bv.z; acc[0][3] += av.x * bv.w;
            acc[1][0] += av.y * bv.x; acc[1][1] += av.y * bv.y; acc[1][2] += av.y * bv.z; acc[1][3] += av.y * bv.w;
            acc[2][0] += av.z * bv.x; acc[2][1] += av.z * bv.y; acc[2][2] += av.z * bv.z; acc[2][3] += av.z * bv.w;
            acc[3][0] += av.w * bv.x; acc[3][1] += av.w * bv.y; acc[3][2] += av.w * bv.z; acc[3][3] += av.w * bv.w;
        }
        __syncthreads();
    }
#pragma unroll
    for (int i = 0; i < 4; i++) {
        int n = n0 + ty * 4 + i;
        if (n < NN) {
            __half2 pair[2];
            pair[0] = __float22half2_rn(make_float2(acc[i][0], acc[i][1]));
            pair[1] = __float22half2_rn(make_float2(acc[i][2], acc[i][3]));
            *(uint2*)&g_projh[((size_t)m * NN + n) * DH + tx * 4] = *(uint2*)pair;
        }
    }
}

// ---------------------------------------------------------------------------
// Kernel 2a: histogram of dst
// ---------------------------------------------------------------------------
__global__ __launch_bounds__(256) void hist_kernel(const int* __restrict__ dst) {
    int gid = blockIdx.x * blockDim.x + threadIdx.x;
    if (gid >= NET) return;
    int m = gid / NE;
    atomicAdd(&g_cnt[m * NN + dst[gid]], 1);
}

// ---------------------------------------------------------------------------
// Kernel 2b: per-chunk sums
// ---------------------------------------------------------------------------
__global__ __launch_bounds__(256) void scan1_kernel() {
    __shared__ int s[256];
    int tid = threadIdx.x;
    int base = blockIdx.x * SCAN_CHUNK + tid * 8;
    int sum = 0;
#pragma unroll
    for (int j = 0; j < 8; j++) {
        int i = base + j;
        if (i < NP) sum += g_cnt[i];
    }
    s[tid] = sum; __syncthreads();
    for (int off = 128; off; off >>= 1) {
        if (tid < off) s[tid] += s[tid + off];
        __syncthreads();
    }
    if (tid == 0) g_blockSums[blockIdx.x] = s[0];
}

// ---------------------------------------------------------------------------
// Kernel 2c: exclusive scan of chunk sums
// ---------------------------------------------------------------------------
__global__ void scan2_kernel() {
    if (threadIdx.x == 0) {
        int run = 0;
        for (int i = 0; i < SCAN_NBLK; i++) { g_blockOff[i] = run; run += g_blockSums[i]; }
    }
}

// ---------------------------------------------------------------------------
// Kernel 2d: per-chunk exclusive scan -> rowStart, cursor
// ---------------------------------------------------------------------------
__global__ __launch_bounds__(256) void scan3_kernel() {
    __shared__ int s[256];
    int tid = threadIdx.x;
    int base = blockIdx.x * SCAN_CHUNK + tid * 8;
    int cnt8[8];
    int sum = 0;
#pragma unroll
    for (int j = 0; j < 8; j++) {
        int i = base + j;
        cnt8[j] = (i < NP) ? g_cnt[i] : 0;
        sum += cnt8[j];
    }
    s[tid] = sum; __syncthreads();
    for (int off = 1; off < 256; off <<= 1) {
        int add = (tid >= off) ? s[tid - off] : 0;
        __syncthreads();
        s[tid] += add;
        __syncthreads();
    }
    int run = g_blockOff[blockIdx.x] + s[tid] - sum;
#pragma unroll
    for (int j = 0; j < 8; j++) {
        int i = base + j;
        if (i < NP) { g_rowStart[i] = run; g_cursor[i] = run; }
        run += cnt8[j];
    }
}

// ---------------------------------------------------------------------------
// Kernel 2e: fill buckets
// ---------------------------------------------------------------------------
__global__ __launch_bounds__(256) void fill_kernel(const int* __restrict__ src,
                                                   const int* __restrict__ dst) {
    int gid = blockIdx.x * blockDim.x + threadIdx.x;
    if (gid >= NET) return;
    int m = gid / NE;
    int pos = atomicAdd(&g_cursor[m * NN + dst[gid]], 1);
    g_eidx[pos] = m * NN + src[gid];
}

// ---------------------------------------------------------------------------
// Kernel 2f: pull-aggregate (fp16 gather, fp32 accum) + finish h.
// 16 threads per node; each owns 4 columns = one 8B load per edge.
// ---------------------------------------------------------------------------
__global__ __launch_bounds__(256) void aggregate_kernel(const float* __restrict__ b,
                                                        const float* __restrict__ prelu_a) {
    long long gid = (long long)blockIdx.x * blockDim.x + threadIdx.x;
    long long node16 = gid >> 4;
    if (node16 >= NP) return;
    int p = (int)node16;
    int part = (int)(gid & 15);
    int rs = g_rowStart[p];
    int c  = g_cnt[p];

    float4 a0 = make_float4(0.f, 0.f, 0.f, 0.f);
    float4 a1 = make_float4(0.f, 0.f, 0.f, 0.f);
    int e = rs, re = rs + c;
    for (; e + 1 < re; e += 2) {
        int i0 = g_eidx[e], i1 = g_eidx[e + 1];
        uint2 r0 = *(const uint2*)&g_projh[(size_t)i0 * DH + part * 4];
        uint2 r1 = *(const uint2*)&g_projh[(size_t)i1 * DH + part * 4];
        float2 lo0 = __half22float2(*(__half2*)&r0.x);
        float2 hi0 = __half22float2(*(__half2*)&r0.y);
        float2 lo1 = __half22float2(*(__half2*)&r1.x);
        float2 hi1 = __half22float2(*(__half2*)&r1.y);
        a0.x += lo0.x; a0.y += lo0.y; a0.z += hi0.x; a0.w += hi0.y;
        a1.x += lo1.x; a1.y += lo1.y; a1.z += hi1.x; a1.w += hi1.y;
    }
    if (e < re) {
        int i0 = g_eidx[e];
        uint2 r0 = *(const uint2*)&g_projh[(size_t)i0 * DH + part * 4];
        float2 lo0 = __half22float2(*(__half2*)&r0.x);
        float2 hi0 = __half22float2(*(__half2*)&r0.y);
        a0.x += lo0.x; a0.y += lo0.y; a0.z += hi0.x; a0.w += hi0.y;
    }
    int m = p / NN;
    float inv = 1.0f / (float)max(c, 1);
    float4 bb = *(const float4*)&b[m * DH + part * 4];
    float a = prelu_a[m];
    float4 h;
    h.x = a0.x + a1.x; h.y = a0.y + a1.y; h.z = a0.z + a1.z; h.w = a0.w + a1.w;
    h.x = h.x * inv + bb.x; h.y = h.y * inv + bb.y; h.z = h.z * inv + bb.z; h.w = h.w * inv + bb.w;
    h.x = (h.x > 0.f) ? h.x : a * h.x;
    h.y = (h.y > 0.f) ? h.y : a * h.y;
    h.z = (h.z > 0.f) ? h.z : a * h.z;
    h.w = (h.w > 0.f) ? h.w : a * h.w;
    *(float4*)&g_h[(size_t)p * DH + part * 4] = h;
}

// ---------------------------------------------------------------------------
// Kernel 3: finalize: s = tanh(h@fcW + fcb); logits[m] += dot(s, attn).
// ---------------------------------------------------------------------------
__global__ __launch_bounds__(256) void finalize_kernel(const float* __restrict__ fc_W,
                                                       const float* __restrict__ fc_b,
                                                       const float* __restrict__ attn) {
    __shared__ __align__(16) float4 sW4[DH / 2][32];
    __shared__ __align__(16) float  sh[8][4][DH];
    __shared__ float sLog[M3];
    const int tid = threadIdx.x;
    const int wid = tid >> 5, lane = tid & 31;

    for (int i = tid; i < (DH / 2) * 32; i += 256) {
        int kk = i >> 5, c = i & 31;
        int k = kk * 2;
        sW4[kk][c] = make_float4(fc_W[k * DH + c],       fc_W[k * DH + c + 32],
                                 fc_W[(k + 1) * DH + c], fc_W[(k + 1) * DH + c + 32]);
    }
    if (tid < M3) sLog[tid] = 0.f;
    __syncthreads();

    const float fcb0 = fc_b[lane],      fcb1 = fc_b[lane + 32];
    const float at0  = attn[lane],      at1  = attn[lane + 32];

    const long long totalGroups = (long long)NP / 4;
    const int totalWarps = gridDim.x * (blockDim.x >> 5);
    float log0 = 0.f, log1 = 0.f, log2 = 0.f;

    for (long long g = (long long)blockIdx.x * (blockDim.x >> 5) + wid;
         g < totalGroups; g += totalWarps) {
        long long p0 = g * 4;
        const int m = (int)(p0 / NN);
        float acc0[4], acc1[4];
#pragma unroll
        for (int j = 0; j < 4; j++) {
            size_t base = (size_t)(p0 + j) * DH;
            sh[wid][j][lane]      = g_h[base + lane];
            sh[wid][j][lane + 32] = g_h[base + lane + 32];
            acc0[j] = fcb0; acc1[j] = fcb1;
        }
        __syncwarp();
#pragma unroll
        for (int kk = 0; kk < DH / 2; kk++) {
            float4 w = sW4[kk][lane];
#pragma unroll
            for (int j = 0; j < 4; j++) {
                float2 hk = *(const float2*)&sh[wid][j][kk * 2];
                acc0[j] += hk.x * w.x + hk.y * w.z;
                acc1[j] += hk.x * w.y + hk.y * w.w;
            }
        }
        float lsum = 0.f;
#pragma unroll
        for (int j = 0; j < 4; j++) {
            float part = tanh_fast(acc0[j]) * at0 + tanh_fast(acc1[j]) * at1;
#pragma unroll
            for (int o = 16; o; o >>= 1) part += __shfl_down_sync(0xffffffffu, part, o);
            lsum += part;
        }
        if (lane == 0) {
            if (m == 0)      log0 += lsum;
            else if (m == 1) log1 += lsum;
            else             log2 += lsum;
        }
        __syncwarp();
    }
    if (lane == 0) {
        if (log0 != 0.f) atomicAdd(&sLog[0], log0);
        if (log1 != 0.f) atomicAdd(&sLog[1], log1);
        if (log2 != 0.f) atomicAdd(&sLog[2], log2);
    }
    __syncthreads();
    if (tid < M3) atomicAdd(&g_logits[tid], sLog[tid]);
}

// ---------------------------------------------------------------------------
// Kernel 4: beta = softmax(logits / N)
// ---------------------------------------------------------------------------
__global__ void beta_kernel() {
    if (threadIdx.x == 0) {
        float l0 = g_logits[0] / (float)NN;
        float l1 = g_logits[1] / (float)NN;
        float l2 = g_logits[2] / (float)NN;
        float mx = fmaxf(l0, fmaxf(l1, l2));
        float e0 = expf(l0 - mx), e1 = expf(l1 - mx), e2 = expf(l2 - mx);
        float s = e0 + e1 + e2;
        g_beta[0] = e0 / s; g_beta[1] = e1 / s; g_beta[2] = e2 / s;
    }
}

// ---------------------------------------------------------------------------
// Kernel 5: z[n][h] = sum_m beta[m] * h[m][n][h]
// ---------------------------------------------------------------------------
__global__ __launch_bounds__(256) void z_kernel(float* __restrict__ out) {
    size_t i = (size_t)blockIdx.x * blockDim.x + threadIdx.x;
    size_t tot = (size_t)NN * DH / 4;
    if (i >= tot) return;
    float b0 = g_beta[0], b1 = g_beta[1], b2 = g_beta[2];
    float4 h0 = ((const float4*)(g_h + (size_t)0 * NN * DH))[i];
    float4 h1 = ((const float4*)(g_h + (size_t)1 * NN * DH))[i];
    float4 h2 = ((const float4*)(g_h + (size_t)2 * NN * DH))[i];
    float4 r;
    r.x = b0 * h0.x + b1 * h1.x + b2 * h2.x;
    r.y = b0 * h0.y + b1 * h1.y + b2 * h2.y;
    r.z = b0 * h0.z + b1 * h1.z + b2 * h2.z;
    r.w = b0 * h0.w + b1 * h1.w + b2 * h2.w;
    ((float4*)out)[i] = r;
}

// ---------------------------------------------------------------------------
extern "C" void kernel_launch(void* const* d_in, const int* in_sizes, int n_in,
                              void* d_out, int out_size) {
    const float* feats   = (const float*)d_in[0];
    const int*   src     = (const int*)  d_in[1];
    const int*   dst     = (const int*)  d_in[2];
    const float* W       = (const float*)d_in[3];
    const float* b       = (const float*)d_in[4];
    const float* prelu_a = (const float*)d_in[5];
    const float* fc_W    = (const float*)d_in[6];
    const float* fc_b    = (const float*)d_in[7];
    const float* attn    = (const float*)d_in[8];
    float* out = (float*)d_out;

    zero_kernel<<<(NP + 255) / 256, 256>>>();
    {
        dim3 grid((NN + 63) / 64, M3);
        proj_kernel<<<grid, 256>>>(feats, W);
    }
    hist_kernel<<<(NET + 255) / 256, 256>>>(dst);
    scan1_kernel<<<SCAN_NBLK, 256>>>();
    scan2_kernel<<<1, 32>>>();
    scan3_kernel<<<SCAN_NBLK, 256>>>();
    fill_kernel<<<(NET + 255) / 256, 256>>>(src, dst);
    {
        long long threads = (long long)NP * 16;
        aggregate_kernel<<<(int)((threads + 255) / 256), 256>>>(b, prelu_a);
    }
    finalize_kernel<<<2048, 256>>>(fc_W, fc_b, attn);
    beta_kernel<<<1, 32>>>();
    {
        size_t tot = (size_t)NN * DH / 4;
        z_kernel<<<(int)((tot + 255) / 256), 256>>>(out);
    }
}

// round 9
// speedup vs baseline: 1.7084x; 1.2104x over previous
#include <cuda_runtime.h>
#include <cuda_fp16.h>
#include <math.h>

#define NN   100000
#define M3   3
#define DIN  128
#define DH   64
#define NE   1600000
#define NP   300000                     // M3*NN rows
#define NET  4800000                    // M3*NE edges
#define SCAN_CHUNK 2048
#define SCAN_NBLK  147                  // ceil(NP/2048)

// ---- scratch (static device allocations; no cudaMalloc allowed) ----
__device__ __half g_projh[(size_t)NP * DH];      // [p][h] fp16
__device__ float g_h   [(size_t)NP * DH];        // post-prelu h
__device__ int   g_cnt [NP];
__device__ int   g_rowStart[NP];
__device__ int   g_cursor[NP];
__device__ int   g_eidx[NET];
__device__ int   g_blockSums[SCAN_NBLK];
__device__ int   g_blockOff [SCAN_NBLK];
__device__ float g_logits[M3];
__device__ float g_beta[M3];

__device__ __forceinline__ float tanh_fast(float x) {
    float y;
    asm("tanh.approx.f32 %0, %1;" : "=f"(y) : "f"(x));
    return y;
}

// ---------------------------------------------------------------------------
// Kernel 0: zero counters + logits
// ---------------------------------------------------------------------------
__global__ void zero_kernel() {
    int i = blockIdx.x * blockDim.x + threadIdx.x;
    if (i < NP) g_cnt[i] = 0;
    if (i < M3) g_logits[i] = 0.f;
}

// ---------------------------------------------------------------------------
// Kernel 1: proj via fp16 tensor-core MMA (fp32 accum, fp16 output).
// Block = 128 threads (4 warps), tile 64 rows x 64 cols, K=128 staged once.
// A smem stride 136 halves, W stride 72 halves: ldmatrix rows shift 16B/row
// mod 128B -> conflict-free.
// ---------------------------------------------------------------------------
__global__ __launch_bounds__(128) void proj_mma_kernel(const float* __restrict__ feats,
                                                       const float* __restrict__ W) {
    __shared__ __align__(16) __half sA[64 * 136];
    __shared__ __align__(16) __half sW[128 * 72];
    const int m  = blockIdx.y;
    const int n0 = blockIdx.x * 64;
    const int tid = threadIdx.x;
    const int wid = tid >> 5, lane = tid & 31;
    const float* fbase = feats + (size_t)m * NN * DIN;
    const float* wbase = W + (size_t)m * DIN * DH;

    // stage A: 64 rows x 128 k  (fp32 -> fp16)
    for (int i = tid; i < 64 * 64; i += 128) {        // 64 float2 per row
        int r = i >> 6, c2 = i & 63;
        float2 v = make_float2(0.f, 0.f);
        if (n0 + r < NN) v = *(const float2*)&fbase[(size_t)(n0 + r) * DIN + c2 * 2];
        *(__half2*)&sA[r * 136 + c2 * 2] = __floats2half2_rn(v.x, v.y);
    }
    // stage W: 128 k x 64 h
    for (int i = tid; i < 128 * 32; i += 128) {       // 32 float2 per row
        int r = i >> 5, c2 = i & 31;
        float2 v = *(const float2*)&wbase[(size_t)r * DH + c2 * 2];
        *(__half2*)&sW[r * 72 + c2 * 2] = __floats2half2_rn(v.x, v.y);
    }
    __syncthreads();

    float c[8][4] = {};                               // 8 n-tiles x 4 f32
    const int rowBase = wid * 16;
    unsigned aBase = (unsigned)__cvta_generic_to_shared(sA);
    unsigned wBase = (unsigned)__cvta_generic_to_shared(sW);

#pragma unroll
    for (int k0 = 0; k0 < 128; k0 += 16) {
        unsigned a0, a1, a2, a3;
        unsigned aAddr = aBase + (unsigned)(((rowBase + (lane & 15)) * 136 + k0 + ((lane >> 4) * 8)) * 2);
        asm volatile("ldmatrix.sync.aligned.m8n8.x4.shared.b16 {%0,%1,%2,%3}, [%4];"
                     : "=r"(a0), "=r"(a1), "=r"(a2), "=r"(a3) : "r"(aAddr));
#pragma unroll
        for (int nt = 0; nt < 8; nt++) {
            unsigned b0, b1;
            unsigned bAddr = wBase + (unsigned)(((k0 + (lane & 15)) * 72 + nt * 8) * 2);
            asm volatile("ldmatrix.sync.aligned.m8n8.x2.trans.shared.b16 {%0,%1}, [%2];"
                         : "=r"(b0), "=r"(b1) : "r"(bAddr));
            asm volatile("mma.sync.aligned.m16n8k16.row.col.f32.f16.f16.f32 "
                         "{%0,%1,%2,%3}, {%4,%5,%6,%7}, {%8,%9}, {%0,%1,%2,%3};"
                         : "+f"(c[nt][0]), "+f"(c[nt][1]), "+f"(c[nt][2]), "+f"(c[nt][3])
                         : "r"(a0), "r"(a1), "r"(a2), "r"(a3), "r"(b0), "r"(b1));
        }
    }

    // epilogue: C fragment -> fp16 global
    int groupID = lane >> 2, tig = lane & 3;
    int r0 = n0 + rowBase + groupID;
    int r1 = r0 + 8;
#pragma unroll
    for (int nt = 0; nt < 8; nt++) {
        int col = nt * 8 + tig * 2;
        if (r0 < NN)
            *(__half2*)&g_projh[((size_t)m * NN + r0) * DH + col] = __floats2half2_rn(c[nt][0], c[nt][1]);
        if (r1 < NN)
            *(__half2*)&g_projh[((size_t)m * NN + r1) * DH + col] = __floats2half2_rn(c[nt][2], c[nt][3]);
    }
}

// ---------------------------------------------------------------------------
// Kernel 2a: histogram of dst
// ---------------------------------------------------------------------------
__global__ __launch_bounds__(256) void hist_kernel(const int* __restrict__ dst) {
    int gid = blockIdx.x * blockDim.x + threadIdx.x;
    if (gid >= NET) return;
    int m = gid / NE;
    atomicAdd(&g_cnt[m * NN + dst[gid]], 1);
}

// ---------------------------------------------------------------------------
// Kernel 2b: per-chunk sums
// ---------------------------------------------------------------------------
__global__ __launch_bounds__(256) void scan1_kernel() {
    __shared__ int s[256];
    int tid = threadIdx.x;
    int base = blockIdx.x * SCAN_CHUNK + tid * 8;
    int sum = 0;
#pragma unroll
    for (int j = 0; j < 8; j++) {
        int i = base + j;
        if (i < NP) sum += g_cnt[i];
    }
    s[tid] = sum; __syncthreads();
    for (int off = 128; off; off >>= 1) {
        if (tid < off) s[tid] += s[tid + off];
        __syncthreads();
    }
    if (tid == 0) g_blockSums[blockIdx.x] = s[0];
}

// ---------------------------------------------------------------------------
// Kernel 2c: exclusive scan of chunk sums
// ---------------------------------------------------------------------------
__global__ void scan2_kernel() {
    if (threadIdx.x == 0) {
        int run = 0;
        for (int i = 0; i < SCAN_NBLK; i++) { g_blockOff[i] = run; run += g_blockSums[i]; }
    }
}

// ---------------------------------------------------------------------------
// Kernel 2d: per-chunk exclusive scan -> rowStart, cursor
// ---------------------------------------------------------------------------
__global__ __launch_bounds__(256) void scan3_kernel() {
    __shared__ int s[256];
    int tid = threadIdx.x;
    int base = blockIdx.x * SCAN_CHUNK + tid * 8;
    int cnt8[8];
    int sum = 0;
#pragma unroll
    for (int j = 0; j < 8; j++) {
        int i = base + j;
        cnt8[j] = (i < NP) ? g_cnt[i] : 0;
        sum += cnt8[j];
    }
    s[tid] = sum; __syncthreads();
    for (int off = 1; off < 256; off <<= 1) {
        int add = (tid >= off) ? s[tid - off] : 0;
        __syncthreads();
        s[tid] += add;
        __syncthreads();
    }
    int run = g_blockOff[blockIdx.x] + s[tid] - sum;
#pragma unroll
    for (int j = 0; j < 8; j++) {
        int i = base + j;
        if (i < NP) { g_rowStart[i] = run; g_cursor[i] = run; }
        run += cnt8[j];
    }
}

// ---------------------------------------------------------------------------
// Kernel 2e: fill buckets
// ---------------------------------------------------------------------------
__global__ __launch_bounds__(256) void fill_kernel(const int* __restrict__ src,
                                                   const int* __restrict__ dst) {
    int gid = blockIdx.x * blockDim.x + threadIdx.x;
    if (gid >= NET) return;
    int m = gid / NE;
    int pos = atomicAdd(&g_cursor[m * NN + dst[gid]], 1);
    g_eidx[pos] = m * NN + src[gid];
}

// ---------------------------------------------------------------------------
// Kernel 2f: pull-aggregate (fp16 gather, fp32 accum) + finish h.
// ---------------------------------------------------------------------------
__global__ __launch_bounds__(256) void aggregate_kernel(const float* __restrict__ b,
                                                        const float* __restrict__ prelu_a) {
    long long gid = (long long)blockIdx.x * blockDim.x + threadIdx.x;
    long long node16 = gid >> 4;
    if (node16 >= NP) return;
    int p = (int)node16;
    int part = (int)(gid & 15);
    int rs = g_rowStart[p];
    int c  = g_cnt[p];

    float4 a0 = make_float4(0.f, 0.f, 0.f, 0.f);
    float4 a1 = make_float4(0.f, 0.f, 0.f, 0.f);
    int e = rs, re = rs + c;
    for (; e + 1 < re; e += 2) {
        int i0 = g_eidx[e], i1 = g_eidx[e + 1];
        uint2 r0 = *(const uint2*)&g_projh[(size_t)i0 * DH + part * 4];
        uint2 r1 = *(const uint2*)&g_projh[(size_t)i1 * DH + part * 4];
        float2 lo0 = __half22float2(*(__half2*)&r0.x);
        float2 hi0 = __half22float2(*(__half2*)&r0.y);
        float2 lo1 = __half22float2(*(__half2*)&r1.x);
        float2 hi1 = __half22float2(*(__half2*)&r1.y);
        a0.x += lo0.x; a0.y += lo0.y; a0.z += hi0.x; a0.w += hi0.y;
        a1.x += lo1.x; a1.y += lo1.y; a1.z += hi1.x; a1.w += hi1.y;
    }
    if (e < re) {
        int i0 = g_eidx[e];
        uint2 r0 = *(const uint2*)&g_projh[(size_t)i0 * DH + part * 4];
        float2 lo0 = __half22float2(*(__half2*)&r0.x);
        float2 hi0 = __half22float2(*(__half2*)&r0.y);
        a0.x += lo0.x; a0.y += lo0.y; a0.z += hi0.x; a0.w += hi0.y;
    }
    int m = p / NN;
    float inv = 1.0f / (float)max(c, 1);
    float4 bb = *(const float4*)&b[m * DH + part * 4];
    float a = prelu_a[m];
    float4 h;
    h.x = a0.x + a1.x; h.y = a0.y + a1.y; h.z = a0.z + a1.z; h.w = a0.w + a1.w;
    h.x = h.x * inv + bb.x; h.y = h.y * inv + bb.y; h.z = h.z * inv + bb.z; h.w = h.w * inv + bb.w;
    h.x = (h.x > 0.f) ? h.x : a * h.x;
    h.y = (h.y > 0.f) ? h.y : a * h.y;
    h.z = (h.z > 0.f) ? h.z : a * h.z;
    h.w = (h.w > 0.f) ? h.w : a * h.w;
    *(float4*)&g_h[(size_t)p * DH + part * 4] = h;
}

// ---------------------------------------------------------------------------
// Kernel 3: finalize: s = tanh(h@fcW + fcb); logits[m] += dot(s, attn).
// ---------------------------------------------------------------------------
__global__ __launch_bounds__(256) void finalize_kernel(const float* __restrict__ fc_W,
                                                       const float* __restrict__ fc_b,
                                                       const float* __restrict__ attn) {
    __shared__ __align__(16) float4 sW4[DH / 2][32];
    __shared__ __align__(16) float  sh[8][4][DH];
    __shared__ float sLog[M3];
    const int tid = threadIdx.x;
    const int wid = tid >> 5, lane = tid & 31;

    for (int i = tid; i < (DH / 2) * 32; i += 256) {
        int kk = i >> 5, c = i & 31;
        int k = kk * 2;
        sW4[kk][c] = make_float4(fc_W[k * DH + c],       fc_W[k * DH + c + 32],
                                 fc_W[(k + 1) * DH + c], fc_W[(k + 1) * DH + c + 32]);
    }
    if (tid < M3) sLog[tid] = 0.f;
    __syncthreads();

    const float fcb0 = fc_b[lane],      fcb1 = fc_b[lane + 32];
    const float at0  = attn[lane],      at1  = attn[lane + 32];

    const long long totalGroups = (long long)NP / 4;
    const int totalWarps = gridDim.x * (blockDim.x >> 5);
    float log0 = 0.f, log1 = 0.f, log2 = 0.f;

    for (long long g = (long long)blockIdx.x * (blockDim.x >> 5) + wid;
         g < totalGroups; g += totalWarps) {
        long long p0 = g * 4;
        const int m = (int)(p0 / NN);
        float acc0[4], acc1[4];
#pragma unroll
        for (int j = 0; j < 4; j++) {
            size_t base = (size_t)(p0 + j) * DH;
            sh[wid][j][lane]      = g_h[base + lane];
            sh[wid][j][lane + 32] = g_h[base + lane + 32];
            acc0[j] = fcb0; acc1[j] = fcb1;
        }
        __syncwarp();
#pragma unroll
        for (int kk = 0; kk < DH / 2; kk++) {
            float4 w = sW4[kk][lane];
#pragma unroll
            for (int j = 0; j < 4; j++) {
                float2 hk = *(const float2*)&sh[wid][j][kk * 2];
                acc0[j] += hk.x * w.x + hk.y * w.z;
                acc1[j] += hk.x * w.y + hk.y * w.w;
            }
        }
        float lsum = 0.f;
#pragma unroll
        for (int j = 0; j < 4; j++) {
            float part = tanh_fast(acc0[j]) * at0 + tanh_fast(acc1[j]) * at1;
#pragma unroll
            for (int o = 16; o; o >>= 1) part += __shfl_down_sync(0xffffffffu, part, o);
            lsum += part;
        }
        if (lane == 0) {
            if (m == 0)      log0 += lsum;
            else if (m == 1) log1 += lsum;
            else             log2 += lsum;
        }
        __syncwarp();
    }
    if (lane == 0) {
        if (log0 != 0.f) atomicAdd(&sLog[0], log0);
        if (log1 != 0.f) atomicAdd(&sLog[1], log1);
        if (log2 != 0.f) atomicAdd(&sLog[2], log2);
    }
    __syncthreads();
    if (tid < M3) atomicAdd(&g_logits[tid], sLog[tid]);
}

// ---------------------------------------------------------------------------
// Kernel 4: beta = softmax(logits / N)
// ---------------------------------------------------------------------------
__global__ void beta_kernel() {
    if (threadIdx.x == 0) {
        float l0 = g_logits[0] / (float)NN;
        float l1 = g_logits[1] / (float)NN;
        float l2 = g_logits[2] / (float)NN;
        float mx = fmaxf(l0, fmaxf(l1, l2));
        float e0 = expf(l0 - mx), e1 = expf(l1 - mx), e2 = expf(l2 - mx);
        float s = e0 + e1 + e2;
        g_beta[0] = e0 / s; g_beta[1] = e1 / s; g_beta[2] = e2 / s;
    }
}

// ---------------------------------------------------------------------------
// Kernel 5: z[n][h] = sum_m beta[m] * h[m][n][h]
// ---------------------------------------------------------------------------
__global__ __launch_bounds__(256) void z_kernel(float* __restrict__ out) {
    size_t i = (size_t)blockIdx.x * blockDim.x + threadIdx.x;
    size_t tot = (size_t)NN * DH / 4;
    if (i >= tot) return;
    float b0 = g_beta[0], b1 = g_beta[1], b2 = g_beta[2];
    float4 h0 = ((const float4*)(g_h + (size_t)0 * NN * DH))[i];
    float4 h1 = ((const float4*)(g_h + (size_t)1 * NN * DH))[i];
    float4 h2 = ((const float4*)(g_h + (size_t)2 * NN * DH))[i];
    float4 r;
    r.x = b0 * h0.x + b1 * h1.x + b2 * h2.x;
    r.y = b0 * h0.y + b1 * h1.y + b2 * h2.y;
    r.z = b0 * h0.z + b1 * h1.z + b2 * h2.z;
    r.w = b0 * h0.w + b1 * h1.w + b2 * h2.w;
    ((float4*)out)[i] = r;
}

// ---------------------------------------------------------------------------
extern "C" void kernel_launch(void* const* d_in, const int* in_sizes, int n_in,
                              void* d_out, int out_size) {
    const float* feats   = (const float*)d_in[0];
    const int*   src     = (const int*)  d_in[1];
    const int*   dst     = (const int*)  d_in[2];
    const float* W       = (const float*)d_in[3];
    const float* b       = (const float*)d_in[4];
    const float* prelu_a = (const float*)d_in[5];
    const float* fc_W    = (const float*)d_in[6];
    const float* fc_b    = (const float*)d_in[7];
    const float* attn    = (const float*)d_in[8];
    float* out = (float*)d_out;

    zero_kernel<<<(NP + 255) / 256, 256>>>();
    {
        dim3 grid((NN + 63) / 64, M3);
        proj_mma_kernel<<<grid, 128>>>(feats, W);
    }
    hist_kernel<<<(NET + 255) / 256, 256>>>(dst);
    scan1_kernel<<<SCAN_NBLK, 256>>>();
    scan2_kernel<<<1, 32>>>();
    scan3_kernel<<<SCAN_NBLK, 256>>>();
    fill_kernel<<<(NET + 255) / 256, 256>>>(src, dst);
    {
        long long threads = (long long)NP * 16;
        aggregate_kernel<<<(int)((threads + 255) / 256), 256>>>(b, prelu_a);
    }
    finalize_kernel<<<2048, 256>>>(fc_W, fc_b, attn);
    beta_kernel<<<1, 32>>>();
    {
        size_t tot = (size_t)NN * DH / 4;
        z_kernel<<<(int)((tot + 255) / 256), 256>>>(out);
    }
}

// round 10
// speedup vs baseline: 1.9877x; 1.1635x over previous
#include <cuda_runtime.h>
#include <cuda_fp16.h>
#include <math.h>

#define NN   100000
#define M3   3
#define DIN  128
#define DH   64
#define NE   1600000
#define NP   300000                     // M3*NN rows
#define NET  4800000                    // M3*NE edges
#define SCAN_CHUNK 2048
#define SCAN_NBLK  147                  // ceil(NP/2048)

// ---- scratch (static device allocations; no cudaMalloc allowed) ----
__device__ __half g_projh[(size_t)NP * DH];      // [p][h] fp16
__device__ float  g_h  [(size_t)NP * DH];        // post-prelu h (fp32, feeds z)
__device__ __half g_hh [(size_t)NP * DH];        // post-prelu h (fp16, feeds finalize MMA)
__device__ int   g_cnt [NP];
__device__ int   g_rowStart[NP];
__device__ int   g_cursor[NP];
__device__ int   g_eidx[NET];
__device__ int   g_blockSums[SCAN_NBLK];
__device__ int   g_blockOff [SCAN_NBLK];
__device__ float g_logits[M3];
__device__ float g_beta[M3];

__device__ __forceinline__ float tanh_fast(float x) {
    float y;
    asm("tanh.approx.f32 %0, %1;" : "=f"(y) : "f"(x));
    return y;
}

// ---------------------------------------------------------------------------
// Kernel 0: zero counters + logits
// ---------------------------------------------------------------------------
__global__ void zero_kernel() {
    int i = blockIdx.x * blockDim.x + threadIdx.x;
    if (i < NP) g_cnt[i] = 0;
    if (i < M3) g_logits[i] = 0.f;
}

// ---------------------------------------------------------------------------
// Kernel 1: proj via fp16 MMA (fp32 accum, fp16 out). 4 warps, 64x64 tile.
// ---------------------------------------------------------------------------
__global__ __launch_bounds__(128) void proj_mma_kernel(const float* __restrict__ feats,
                                                       const float* __restrict__ W) {
    __shared__ __align__(16) __half sA[64 * 136];
    __shared__ __align__(16) __half sW[128 * 72];
    const int m  = blockIdx.y;
    const int n0 = blockIdx.x * 64;
    const int tid = threadIdx.x;
    const int wid = tid >> 5, lane = tid & 31;
    const float* fbase = feats + (size_t)m * NN * DIN;
    const float* wbase = W + (size_t)m * DIN * DH;

    for (int i = tid; i < 64 * 64; i += 128) {
        int r = i >> 6, c2 = i & 63;
        float2 v = make_float2(0.f, 0.f);
        if (n0 + r < NN) v = *(const float2*)&fbase[(size_t)(n0 + r) * DIN + c2 * 2];
        *(__half2*)&sA[r * 136 + c2 * 2] = __floats2half2_rn(v.x, v.y);
    }
    for (int i = tid; i < 128 * 32; i += 128) {
        int r = i >> 5, c2 = i & 31;
        float2 v = *(const float2*)&wbase[(size_t)r * DH + c2 * 2];
        *(__half2*)&sW[r * 72 + c2 * 2] = __floats2half2_rn(v.x, v.y);
    }
    __syncthreads();

    float c[8][4] = {};
    const int rowBase = wid * 16;
    unsigned aBase = (unsigned)__cvta_generic_to_shared(sA);
    unsigned wBase = (unsigned)__cvta_generic_to_shared(sW);

#pragma unroll
    for (int k0 = 0; k0 < 128; k0 += 16) {
        unsigned a0, a1, a2, a3;
        unsigned aAddr = aBase + (unsigned)(((rowBase + (lane & 15)) * 136 + k0 + ((lane >> 4) * 8)) * 2);
        asm volatile("ldmatrix.sync.aligned.m8n8.x4.shared.b16 {%0,%1,%2,%3}, [%4];"
                     : "=r"(a0), "=r"(a1), "=r"(a2), "=r"(a3) : "r"(aAddr));
#pragma unroll
        for (int nt = 0; nt < 8; nt++) {
            unsigned b0, b1;
            unsigned bAddr = wBase + (unsigned)(((k0 + (lane & 15)) * 72 + nt * 8) * 2);
            asm volatile("ldmatrix.sync.aligned.m8n8.x2.trans.shared.b16 {%0,%1}, [%2];"
                         : "=r"(b0), "=r"(b1) : "r"(bAddr));
            asm volatile("mma.sync.aligned.m16n8k16.row.col.f32.f16.f16.f32 "
                         "{%0,%1,%2,%3}, {%4,%5,%6,%7}, {%8,%9}, {%0,%1,%2,%3};"
                         : "+f"(c[nt][0]), "+f"(c[nt][1]), "+f"(c[nt][2]), "+f"(c[nt][3])
                         : "r"(a0), "r"(a1), "r"(a2), "r"(a3), "r"(b0), "r"(b1));
        }
    }

    int groupID = lane >> 2, tig = lane & 3;
    int r0 = n0 + rowBase + groupID;
    int r1 = r0 + 8;
#pragma unroll
    for (int nt = 0; nt < 8; nt++) {
        int col = nt * 8 + tig * 2;
        if (r0 < NN)
            *(__half2*)&g_projh[((size_t)m * NN + r0) * DH + col] = __floats2half2_rn(c[nt][0], c[nt][1]);
        if (r1 < NN)
            *(__half2*)&g_projh[((size_t)m * NN + r1) * DH + col] = __floats2half2_rn(c[nt][2], c[nt][3]);
    }
}

// ---------------------------------------------------------------------------
// Kernel 2a: histogram of dst
// ---------------------------------------------------------------------------
__global__ __launch_bounds__(256) void hist_kernel(const int* __restrict__ dst) {
    int gid = blockIdx.x * blockDim.x + threadIdx.x;
    if (gid >= NET) return;
    int m = gid / NE;
    atomicAdd(&g_cnt[m * NN + dst[gid]], 1);
}

// ---------------------------------------------------------------------------
// Kernel 2b/2c/2d: scan
// ---------------------------------------------------------------------------
__global__ __launch_bounds__(256) void scan1_kernel() {
    __shared__ int s[256];
    int tid = threadIdx.x;
    int base = blockIdx.x * SCAN_CHUNK + tid * 8;
    int sum = 0;
#pragma unroll
    for (int j = 0; j < 8; j++) {
        int i = base + j;
        if (i < NP) sum += g_cnt[i];
    }
    s[tid] = sum; __syncthreads();
    for (int off = 128; off; off >>= 1) {
        if (tid < off) s[tid] += s[tid + off];
        __syncthreads();
    }
    if (tid == 0) g_blockSums[blockIdx.x] = s[0];
}

__global__ void scan2_kernel() {
    if (threadIdx.x == 0) {
        int run = 0;
        for (int i = 0; i < SCAN_NBLK; i++) { g_blockOff[i] = run; run += g_blockSums[i]; }
    }
}

__global__ __launch_bounds__(256) void scan3_kernel() {
    __shared__ int s[256];
    int tid = threadIdx.x;
    int base = blockIdx.x * SCAN_CHUNK + tid * 8;
    int cnt8[8];
    int sum = 0;
#pragma unroll
    for (int j = 0; j < 8; j++) {
        int i = base + j;
        cnt8[j] = (i < NP) ? g_cnt[i] : 0;
        sum += cnt8[j];
    }
    s[tid] = sum; __syncthreads();
    for (int off = 1; off < 256; off <<= 1) {
        int add = (tid >= off) ? s[tid - off] : 0;
        __syncthreads();
        s[tid] += add;
        __syncthreads();
    }
    int run = g_blockOff[blockIdx.x] + s[tid] - sum;
#pragma unroll
    for (int j = 0; j < 8; j++) {
        int i = base + j;
        if (i < NP) { g_rowStart[i] = run; g_cursor[i] = run; }
        run += cnt8[j];
    }
}

// ---------------------------------------------------------------------------
// Kernel 2e: fill buckets
// ---------------------------------------------------------------------------
__global__ __launch_bounds__(256) void fill_kernel(const int* __restrict__ src,
                                                   const int* __restrict__ dst) {
    int gid = blockIdx.x * blockDim.x + threadIdx.x;
    if (gid >= NET) return;
    int m = gid / NE;
    int pos = atomicAdd(&g_cursor[m * NN + dst[gid]], 1);
    g_eidx[pos] = m * NN + src[gid];
}

// ---------------------------------------------------------------------------
// Kernel 2f: pull-aggregate + finish h (fp32 + fp16 copies).
// ---------------------------------------------------------------------------
__global__ __launch_bounds__(256) void aggregate_kernel(const float* __restrict__ b,
                                                        const float* __restrict__ prelu_a) {
    long long gid = (long long)blockIdx.x * blockDim.x + threadIdx.x;
    long long node16 = gid >> 4;
    if (node16 >= NP) return;
    int p = (int)node16;
    int part = (int)(gid & 15);
    int rs = g_rowStart[p];
    int c  = g_cnt[p];

    float4 a0 = make_float4(0.f, 0.f, 0.f, 0.f);
    float4 a1 = make_float4(0.f, 0.f, 0.f, 0.f);
    int e = rs, re = rs + c;
    for (; e + 1 < re; e += 2) {
        int i0 = g_eidx[e], i1 = g_eidx[e + 1];
        uint2 r0 = *(const uint2*)&g_projh[(size_t)i0 * DH + part * 4];
        uint2 r1 = *(const uint2*)&g_projh[(size_t)i1 * DH + part * 4];
        float2 lo0 = __half22float2(*(__half2*)&r0.x);
        float2 hi0 = __half22float2(*(__half2*)&r0.y);
        float2 lo1 = __half22float2(*(__half2*)&r1.x);
        float2 hi1 = __half22float2(*(__half2*)&r1.y);
        a0.x += lo0.x; a0.y += lo0.y; a0.z += hi0.x; a0.w += hi0.y;
        a1.x += lo1.x; a1.y += lo1.y; a1.z += hi1.x; a1.w += hi1.y;
    }
    if (e < re) {
        int i0 = g_eidx[e];
        uint2 r0 = *(const uint2*)&g_projh[(size_t)i0 * DH + part * 4];
        float2 lo0 = __half22float2(*(__half2*)&r0.x);
        float2 hi0 = __half22float2(*(__half2*)&r0.y);
        a0.x += lo0.x; a0.y += lo0.y; a0.z += hi0.x; a0.w += hi0.y;
    }
    int m = p / NN;
    float inv = 1.0f / (float)max(c, 1);
    float4 bb = *(const float4*)&b[m * DH + part * 4];
    float a = prelu_a[m];
    float4 h;
    h.x = a0.x + a1.x; h.y = a0.y + a1.y; h.z = a0.z + a1.z; h.w = a0.w + a1.w;
    h.x = h.x * inv + bb.x; h.y = h.y * inv + bb.y; h.z = h.z * inv + bb.z; h.w = h.w * inv + bb.w;
    h.x = (h.x > 0.f) ? h.x : a * h.x;
    h.y = (h.y > 0.f) ? h.y : a * h.y;
    h.z = (h.z > 0.f) ? h.z : a * h.z;
    h.w = (h.w > 0.f) ? h.w : a * h.w;
    *(float4*)&g_h[(size_t)p * DH + part * 4] = h;
    __half2 ph[2];
    ph[0] = __floats2half2_rn(h.x, h.y);
    ph[1] = __floats2half2_rn(h.z, h.w);
    *(uint2*)&g_hh[(size_t)p * DH + part * 4] = *(uint2*)ph;
}

// ---------------------------------------------------------------------------
// Kernel 3: finalize via fp16 MMA. 64-row tile, K=64, fcW staged fp16.
// s = tanh(h@fcW + fcb); logits[m] += sum_rows dot(s_row, attn).
// ---------------------------------------------------------------------------
__global__ __launch_bounds__(128) void finalize_mma(const float* __restrict__ fc_W,
                                                    const float* __restrict__ fc_b,
                                                    const float* __restrict__ attn) {
    __shared__ __align__(16) __half sH[64 * 72];
    __shared__ __align__(16) __half sW[64 * 72];
    __shared__ float sLog[2];
    const int tid = threadIdx.x;
    const int wid = tid >> 5, lane = tid & 31;
    const long long p0 = (long long)blockIdx.x * 64;
    const int m0 = (int)(p0 / NN);

    for (int i = tid; i < 64 * 32; i += 128) {       // fcW [k][n] fp16
        int r = i >> 5, c2 = i & 31;
        float2 v = *(const float2*)&fc_W[r * DH + c2 * 2];
        *(__half2*)&sW[r * 72 + c2 * 2] = __floats2half2_rn(v.x, v.y);
    }
    for (int i = tid; i < 64 * 8; i += 128) {        // h rows, 8 x uint4 per row
        int r = i >> 3, c4 = i & 7;
        long long p = p0 + r;
        uint4 v = make_uint4(0, 0, 0, 0);
        if (p < NP) v = *(const uint4*)&g_hh[(size_t)p * DH + c4 * 8];
        *(uint4*)&sH[r * 72 + c4 * 8] = v;
    }
    if (tid < 2) sLog[tid] = 0.f;
    __syncthreads();

    float c[8][4] = {};
    const int rowBase = wid * 16;
    unsigned hBase = (unsigned)__cvta_generic_to_shared(sH);
    unsigned wBase = (unsigned)__cvta_generic_to_shared(sW);

#pragma unroll
    for (int k0 = 0; k0 < 64; k0 += 16) {
        unsigned a0, a1, a2, a3;
        unsigned aAddr = hBase + (unsigned)(((rowBase + (lane & 15)) * 72 + k0 + ((lane >> 4) * 8)) * 2);
        asm volatile("ldmatrix.sync.aligned.m8n8.x4.shared.b16 {%0,%1,%2,%3}, [%4];"
                     : "=r"(a0), "=r"(a1), "=r"(a2), "=r"(a3) : "r"(aAddr));
#pragma unroll
        for (int nt = 0; nt < 8; nt++) {
            unsigned b0, b1;
            unsigned bAddr = wBase + (unsigned)(((k0 + (lane & 15)) * 72 + nt * 8) * 2);
            asm volatile("ldmatrix.sync.aligned.m8n8.x2.trans.shared.b16 {%0,%1}, [%2];"
                         : "=r"(b0), "=r"(b1) : "r"(bAddr));
            asm volatile("mma.sync.aligned.m16n8k16.row.col.f32.f16.f16.f32 "
                         "{%0,%1,%2,%3}, {%4,%5,%6,%7}, {%8,%9}, {%0,%1,%2,%3};"
                         : "+f"(c[nt][0]), "+f"(c[nt][1]), "+f"(c[nt][2]), "+f"(c[nt][3])
                         : "r"(a0), "r"(a1), "r"(a2), "r"(a3), "r"(b0), "r"(b1));
        }
    }

    // epilogue: + fc_b, tanh, dot attn, reduce
    int groupID = lane >> 2, tig = lane & 3;
    long long pr0 = p0 + rowBase + groupID;
    long long pr1 = pr0 + 8;
    float s0 = 0.f, s1 = 0.f;
#pragma unroll
    for (int nt = 0; nt < 8; nt++) {
        int col = nt * 8 + tig * 2;
        float fb0 = fc_b[col], fb1 = fc_b[col + 1];
        float av0 = attn[col], av1 = attn[col + 1];
        s0 += tanh_fast(c[nt][0] + fb0) * av0 + tanh_fast(c[nt][1] + fb1) * av1;
        s1 += tanh_fast(c[nt][2] + fb0) * av0 + tanh_fast(c[nt][3] + fb1) * av1;
    }
#pragma unroll
    for (int o = 1; o < 4; o <<= 1) {
        s0 += __shfl_xor_sync(0xffffffffu, s0, o);
        s1 += __shfl_xor_sync(0xffffffffu, s1, o);
    }
    if (tig == 0) {
        float c0 = (pr0 < NP) ? s0 : 0.f;
        float c1 = (pr1 < NP) ? s1 : 0.f;
        int mA = (int)(pr0 / NN), mB = (int)(pr1 / NN);
        float add0 = ((mA == m0) ? c0 : 0.f) + ((mB == m0) ? c1 : 0.f);
        float add1 = ((mA != m0) ? c0 : 0.f) + ((mB != m0) ? c1 : 0.f);
        if (add0 != 0.f) atomicAdd(&sLog[0], add0);
        if (add1 != 0.f) atomicAdd(&sLog[1], add1);
    }
    __syncthreads();
    if (tid == 0) {
        if (sLog[0] != 0.f) atomicAdd(&g_logits[m0], sLog[0]);
        if (m0 + 1 < M3 && sLog[1] != 0.f) atomicAdd(&g_logits[m0 + 1], sLog[1]);
    }
}

// ---------------------------------------------------------------------------
// Kernel 4: beta = softmax(logits / N)
// ---------------------------------------------------------------------------
__global__ void beta_kernel() {
    if (threadIdx.x == 0) {
        float l0 = g_logits[0] / (float)NN;
        float l1 = g_logits[1] / (float)NN;
        float l2 = g_logits[2] / (float)NN;
        float mx = fmaxf(l0, fmaxf(l1, l2));
        float e0 = expf(l0 - mx), e1 = expf(l1 - mx), e2 = expf(l2 - mx);
        float s = e0 + e1 + e2;
        g_beta[0] = e0 / s; g_beta[1] = e1 / s; g_beta[2] = e2 / s;
    }
}

// ---------------------------------------------------------------------------
// Kernel 5: z[n][h] = sum_m beta[m] * h[m][n][h]   (fp32 h)
// ---------------------------------------------------------------------------
__global__ __launch_bounds__(256) void z_kernel(float* __restrict__ out) {
    size_t i = (size_t)blockIdx.x * blockDim.x + threadIdx.x;
    size_t tot = (size_t)NN * DH / 4;
    if (i >= tot) return;
    float b0 = g_beta[0], b1 = g_beta[1], b2 = g_beta[2];
    float4 h0 = ((const float4*)(g_h + (size_t)0 * NN * DH))[i];
    float4 h1 = ((const float4*)(g_h + (size_t)1 * NN * DH))[i];
    float4 h2 = ((const float4*)(g_h + (size_t)2 * NN * DH))[i];
    float4 r;
    r.x = b0 * h0.x + b1 * h1.x + b2 * h2.x;
    r.y = b0 * h0.y + b1 * h1.y + b2 * h2.y;
    r.z = b0 * h0.z + b1 * h1.z + b2 * h2.z;
    r.w = b0 * h0.w + b1 * h1.w + b2 * h2.w;
    ((float4*)out)[i] = r;
}

// ---------------------------------------------------------------------------
extern "C" void kernel_launch(void* const* d_in, const int* in_sizes, int n_in,
                              void* d_out, int out_size) {
    const float* feats   = (const float*)d_in[0];
    const int*   src     = (const int*)  d_in[1];
    const int*   dst     = (const int*)  d_in[2];
    const float* W       = (const float*)d_in[3];
    const float* b       = (const float*)d_in[4];
    const float* prelu_a = (const float*)d_in[5];
    const float* fc_W    = (const float*)d_in[6];
    const float* fc_b    = (const float*)d_in[7];
    const float* attn    = (const float*)d_in[8];
    float* out = (float*)d_out;

    zero_kernel<<<(NP + 255) / 256, 256>>>();
    {
        dim3 grid((NN + 63) / 64, M3);
        proj_mma_kernel<<<grid, 128>>>(feats, W);
    }
    hist_kernel<<<(NET + 255) / 256, 256>>>(dst);
    scan1_kernel<<<SCAN_NBLK, 256>>>();
    scan2_kernel<<<1, 32>>>();
    scan3_kernel<<<SCAN_NBLK, 256>>>();
    fill_kernel<<<(NET + 255) / 256, 256>>>(src, dst);
    {
        long long threads = (long long)NP * 16;
        aggregate_kernel<<<(int)((threads + 255) / 256), 256>>>(b, prelu_a);
    }
    finalize_mma<<<(NP + 63) / 64, 128>>>(fc_W, fc_b, attn);
    beta_kernel<<<1, 32>>>();
    {
        size_t tot = (size_t)NN * DH / 4;
        z_kernel<<<(int)((tot + 255) / 256), 256>>>(out);
    }
}

// round 11
// speedup vs baseline: 2.1474x; 1.0804x over previous
#include <cuda_runtime.h>
#include <cuda_fp16.h>
#include <math.h>

#define NN   100000
#define M3   3
#define DIN  128
#define DH   64
#define NE   1600000
#define NP   300000                     // M3*NN rows
#define NET  4800000                    // M3*NE edges
#define SCAN_CHUNK 2048
#define SCAN_NBLK  147                  // ceil(NP/2048)

// ---- scratch (static device allocations; no cudaMalloc allowed) ----
__device__ __half g_projh[(size_t)NP * DH];      // [p][h] fp16
__device__ float  g_h  [(size_t)NP * DH];        // post-prelu h (fp32, feeds z)
__device__ __half g_hh [(size_t)NP * DH];        // post-prelu h (fp16, feeds finalize MMA)
__device__ int   g_cnt [NP];
__device__ int   g_rowStart[NP];
__device__ int   g_cursor[NP];
__device__ int   g_eidx[NET];
__device__ int   g_blockSums[SCAN_NBLK];
__device__ int   g_blockOff [SCAN_NBLK];
__device__ float g_logits[M3];
__device__ float g_beta[M3];

__device__ __forceinline__ float tanh_fast(float x) {
    float y;
    asm("tanh.approx.f32 %0, %1;" : "=f"(y) : "f"(x));
    return y;
}

// ---------------------------------------------------------------------------
// Kernel 0: zero counters + logits
// ---------------------------------------------------------------------------
__global__ void zero_kernel() {
    int i = blockIdx.x * blockDim.x + threadIdx.x;
    if (i < NP) g_cnt[i] = 0;
    if (i < M3) g_logits[i] = 0.f;
}

// ---------------------------------------------------------------------------
// Kernel 1: proj via fp16 MMA (fp32 accum, fp16 out). 4 warps, 64x64 tile.
// ---------------------------------------------------------------------------
__global__ __launch_bounds__(128) void proj_mma_kernel(const float* __restrict__ feats,
                                                       const float* __restrict__ W) {
    __shared__ __align__(16) __half sA[64 * 136];
    __shared__ __align__(16) __half sW[128 * 72];
    const int m  = blockIdx.y;
    const int n0 = blockIdx.x * 64;
    const int tid = threadIdx.x;
    const int wid = tid >> 5, lane = tid & 31;
    const float* fbase = feats + (size_t)m * NN * DIN;
    const float* wbase = W + (size_t)m * DIN * DH;

    for (int i = tid; i < 64 * 64; i += 128) {
        int r = i >> 6, c2 = i & 63;
        float2 v = make_float2(0.f, 0.f);
        if (n0 + r < NN) v = *(const float2*)&fbase[(size_t)(n0 + r) * DIN + c2 * 2];
        *(__half2*)&sA[r * 136 + c2 * 2] = __floats2half2_rn(v.x, v.y);
    }
    for (int i = tid; i < 128 * 32; i += 128) {
        int r = i >> 5, c2 = i & 31;
        float2 v = *(const float2*)&wbase[(size_t)r * DH + c2 * 2];
        *(__half2*)&sW[r * 72 + c2 * 2] = __floats2half2_rn(v.x, v.y);
    }
    __syncthreads();

    float c[8][4] = {};
    const int rowBase = wid * 16;
    unsigned aBase = (unsigned)__cvta_generic_to_shared(sA);
    unsigned wBase = (unsigned)__cvta_generic_to_shared(sW);

#pragma unroll
    for (int k0 = 0; k0 < 128; k0 += 16) {
        unsigned a0, a1, a2, a3;
        unsigned aAddr = aBase + (unsigned)(((rowBase + (lane & 15)) * 136 + k0 + ((lane >> 4) * 8)) * 2);
        asm volatile("ldmatrix.sync.aligned.m8n8.x4.shared.b16 {%0,%1,%2,%3}, [%4];"
                     : "=r"(a0), "=r"(a1), "=r"(a2), "=r"(a3) : "r"(aAddr));
#pragma unroll
        for (int nt = 0; nt < 8; nt++) {
            unsigned b0, b1;
            unsigned bAddr = wBase + (unsigned)(((k0 + (lane & 15)) * 72 + nt * 8) * 2);
            asm volatile("ldmatrix.sync.aligned.m8n8.x2.trans.shared.b16 {%0,%1}, [%2];"
                         : "=r"(b0), "=r"(b1) : "r"(bAddr));
            asm volatile("mma.sync.aligned.m16n8k16.row.col.f32.f16.f16.f32 "
                         "{%0,%1,%2,%3}, {%4,%5,%6,%7}, {%8,%9}, {%0,%1,%2,%3};"
                         : "+f"(c[nt][0]), "+f"(c[nt][1]), "+f"(c[nt][2]), "+f"(c[nt][3])
                         : "r"(a0), "r"(a1), "r"(a2), "r"(a3), "r"(b0), "r"(b1));
        }
    }

    int groupID = lane >> 2, tig = lane & 3;
    int r0 = n0 + rowBase + groupID;
    int r1 = r0 + 8;
#pragma unroll
    for (int nt = 0; nt < 8; nt++) {
        int col = nt * 8 + tig * 2;
        if (r0 < NN)
            *(__half2*)&g_projh[((size_t)m * NN + r0) * DH + col] = __floats2half2_rn(c[nt][0], c[nt][1]);
        if (r1 < NN)
            *(__half2*)&g_projh[((size_t)m * NN + r1) * DH + col] = __floats2half2_rn(c[nt][2], c[nt][3]);
    }
}

// ---------------------------------------------------------------------------
// Kernel 2a: histogram of dst
// ---------------------------------------------------------------------------
__global__ __launch_bounds__(256) void hist_kernel(const int* __restrict__ dst) {
    int gid = blockIdx.x * blockDim.x + threadIdx.x;
    if (gid >= NET) return;
    int m = gid / NE;
    atomicAdd(&g_cnt[m * NN + dst[gid]], 1);
}

// ---------------------------------------------------------------------------
// Kernel 2b/2c/2d: scan
// ---------------------------------------------------------------------------
__global__ __launch_bounds__(256) void scan1_kernel() {
    __shared__ int s[256];
    int tid = threadIdx.x;
    int base = blockIdx.x * SCAN_CHUNK + tid * 8;
    int sum = 0;
#pragma unroll
    for (int j = 0; j < 8; j++) {
        int i = base + j;
        if (i < NP) sum += g_cnt[i];
    }
    s[tid] = sum; __syncthreads();
    for (int off = 128; off; off >>= 1) {
        if (tid < off) s[tid] += s[tid + off];
        __syncthreads();
    }
    if (tid == 0) g_blockSums[blockIdx.x] = s[0];
}

__global__ void scan2_kernel() {
    if (threadIdx.x == 0) {
        int run = 0;
        for (int i = 0; i < SCAN_NBLK; i++) { g_blockOff[i] = run; run += g_blockSums[i]; }
    }
}

__global__ __launch_bounds__(256) void scan3_kernel() {
    __shared__ int s[256];
    int tid = threadIdx.x;
    int base = blockIdx.x * SCAN_CHUNK + tid * 8;
    int cnt8[8];
    int sum = 0;
#pragma unroll
    for (int j = 0; j < 8; j++) {
        int i = base + j;
        cnt8[j] = (i < NP) ? g_cnt[i] : 0;
        sum += cnt8[j];
    }
    s[tid] = sum; __syncthreads();
    for (int off = 1; off < 256; off <<= 1) {
        int add = (tid >= off) ? s[tid - off] : 0;
        __syncthreads();
        s[tid] += add;
        __syncthreads();
    }
    int run = g_blockOff[blockIdx.x] + s[tid] - sum;
#pragma unroll
    for (int j = 0; j < 8; j++) {
        int i = base + j;
        if (i < NP) { g_rowStart[i] = run; g_cursor[i] = run; }
        run += cnt8[j];
    }
}

// ---------------------------------------------------------------------------
// Kernel 2e: fill buckets
// ---------------------------------------------------------------------------
__global__ __launch_bounds__(256) void fill_kernel(const int* __restrict__ src,
                                                   const int* __restrict__ dst) {
    int gid = blockIdx.x * blockDim.x + threadIdx.x;
    if (gid >= NET) return;
    int m = gid / NE;
    int pos = atomicAdd(&g_cursor[m * NN + dst[gid]], 1);
    g_eidx[pos] = m * NN + src[gid];
}

// ---------------------------------------------------------------------------
// Kernel 2f: pull-aggregate v2: 8 threads/node, uint4 (16B) fp16 gathers.
// ---------------------------------------------------------------------------
__global__ __launch_bounds__(256) void aggregate_kernel(const float* __restrict__ b,
                                                        const float* __restrict__ prelu_a) {
    long long gid = (long long)blockIdx.x * blockDim.x + threadIdx.x;
    long long node8 = gid >> 3;
    if (node8 >= NP) return;
    int p = (int)node8;
    int part = (int)(gid & 7);          // owns cols [part*8, part*8+8)
    int rs = g_rowStart[p];
    int c  = g_cnt[p];

    float acc[8] = {};
    int e = rs, re = rs + c;
    for (; e + 1 < re; e += 2) {
        int i0 = g_eidx[e], i1 = g_eidx[e + 1];
        uint4 r0 = *(const uint4*)&g_projh[(size_t)i0 * DH + part * 8];
        uint4 r1 = *(const uint4*)&g_projh[(size_t)i1 * DH + part * 8];
        float2 t;
        t = __half22float2(*(__half2*)&r0.x); acc[0] += t.x; acc[1] += t.y;
        t = __half22float2(*(__half2*)&r0.y); acc[2] += t.x; acc[3] += t.y;
        t = __half22float2(*(__half2*)&r0.z); acc[4] += t.x; acc[5] += t.y;
        t = __half22float2(*(__half2*)&r0.w); acc[6] += t.x; acc[7] += t.y;
        t = __half22float2(*(__half2*)&r1.x); acc[0] += t.x; acc[1] += t.y;
        t = __half22float2(*(__half2*)&r1.y); acc[2] += t.x; acc[3] += t.y;
        t = __half22float2(*(__half2*)&r1.z); acc[4] += t.x; acc[5] += t.y;
        t = __half22float2(*(__half2*)&r1.w); acc[6] += t.x; acc[7] += t.y;
    }
    if (e < re) {
        int i0 = g_eidx[e];
        uint4 r0 = *(const uint4*)&g_projh[(size_t)i0 * DH + part * 8];
        float2 t;
        t = __half22float2(*(__half2*)&r0.x); acc[0] += t.x; acc[1] += t.y;
        t = __half22float2(*(__half2*)&r0.y); acc[2] += t.x; acc[3] += t.y;
        t = __half22float2(*(__half2*)&r0.z); acc[4] += t.x; acc[5] += t.y;
        t = __half22float2(*(__half2*)&r0.w); acc[6] += t.x; acc[7] += t.y;
    }
    int m = p / NN;
    float inv = 1.0f / (float)max(c, 1);
    float a = prelu_a[m];
    float4 b0 = *(const float4*)&b[m * DH + part * 8];
    float4 b1 = *(const float4*)&b[m * DH + part * 8 + 4];
    float h[8];
    h[0] = acc[0] * inv + b0.x; h[1] = acc[1] * inv + b0.y;
    h[2] = acc[2] * inv + b0.z; h[3] = acc[3] * inv + b0.w;
    h[4] = acc[4] * inv + b1.x; h[5] = acc[5] * inv + b1.y;
    h[6] = acc[6] * inv + b1.z; h[7] = acc[7] * inv + b1.w;
#pragma unroll
    for (int j = 0; j < 8; j++) h[j] = (h[j] > 0.f) ? h[j] : a * h[j];
    *(float4*)&g_h[(size_t)p * DH + part * 8]     = make_float4(h[0], h[1], h[2], h[3]);
    *(float4*)&g_h[(size_t)p * DH + part * 8 + 4] = make_float4(h[4], h[5], h[6], h[7]);
    __half2 ph[4];
    ph[0] = __floats2half2_rn(h[0], h[1]);
    ph[1] = __floats2half2_rn(h[2], h[3]);
    ph[2] = __floats2half2_rn(h[4], h[5]);
    ph[3] = __floats2half2_rn(h[6], h[7]);
    *(uint4*)&g_hh[(size_t)p * DH + part * 8] = *(uint4*)ph;
}

// ---------------------------------------------------------------------------
// Kernel 3: finalize via fp16 MMA.
// ---------------------------------------------------------------------------
__global__ __launch_bounds__(128) void finalize_mma(const float* __restrict__ fc_W,
                                                    const float* __restrict__ fc_b,
                                                    const float* __restrict__ attn) {
    __shared__ __align__(16) __half sH[64 * 72];
    __shared__ __align__(16) __half sW[64 * 72];
    __shared__ float sLog[2];
    const int tid = threadIdx.x;
    const int wid = tid >> 5, lane = tid & 31;
    const long long p0 = (long long)blockIdx.x * 64;
    const int m0 = (int)(p0 / NN);

    for (int i = tid; i < 64 * 32; i += 128) {
        int r = i >> 5, c2 = i & 31;
        float2 v = *(const float2*)&fc_W[r * DH + c2 * 2];
        *(__half2*)&sW[r * 72 + c2 * 2] = __floats2half2_rn(v.x, v.y);
    }
    for (int i = tid; i < 64 * 8; i += 128) {
        int r = i >> 3, c4 = i & 7;
        long long p = p0 + r;
        uint4 v = make_uint4(0, 0, 0, 0);
        if (p < NP) v = *(const uint4*)&g_hh[(size_t)p * DH + c4 * 8];
        *(uint4*)&sH[r * 72 + c4 * 8] = v;
    }
    if (tid < 2) sLog[tid] = 0.f;
    __syncthreads();

    float c[8][4] = {};
    const int rowBase = wid * 16;
    unsigned hBase = (unsigned)__cvta_generic_to_shared(sH);
    unsigned wBase = (unsigned)__cvta_generic_to_shared(sW);

#pragma unroll
    for (int k0 = 0; k0 < 64; k0 += 16) {
        unsigned a0, a1, a2, a3;
        unsigned aAddr = hBase + (unsigned)(((rowBase + (lane & 15)) * 72 + k0 + ((lane >> 4) * 8)) * 2);
        asm volatile("ldmatrix.sync.aligned.m8n8.x4.shared.b16 {%0,%1,%2,%3}, [%4];"
                     : "=r"(a0), "=r"(a1), "=r"(a2), "=r"(a3) : "r"(aAddr));
#pragma unroll
        for (int nt = 0; nt < 8; nt++) {
            unsigned b0, b1;
            unsigned bAddr = wBase + (unsigned)(((k0 + (lane & 15)) * 72 + nt * 8) * 2);
            asm volatile("ldmatrix.sync.aligned.m8n8.x2.trans.shared.b16 {%0,%1}, [%2];"
                         : "=r"(b0), "=r"(b1) : "r"(bAddr));
            asm volatile("mma.sync.aligned.m16n8k16.row.col.f32.f16.f16.f32 "
                         "{%0,%1,%2,%3}, {%4,%5,%6,%7}, {%8,%9}, {%0,%1,%2,%3};"
                         : "+f"(c[nt][0]), "+f"(c[nt][1]), "+f"(c[nt][2]), "+f"(c[nt][3])
                         : "r"(a0), "r"(a1), "r"(a2), "r"(a3), "r"(b0), "r"(b1));
        }
    }

    int groupID = lane >> 2, tig = lane & 3;
    long long pr0 = p0 + rowBase + groupID;
    long long pr1 = pr0 + 8;
    float s0 = 0.f, s1 = 0.f;
#pragma unroll
    for (int nt = 0; nt < 8; nt++) {
        int col = nt * 8 + tig * 2;
        float fb0 = fc_b[col], fb1 = fc_b[col + 1];
        float av0 = attn[col], av1 = attn[col + 1];
        s0 += tanh_fast(c[nt][0] + fb0) * av0 + tanh_fast(c[nt][1] + fb1) * av1;
        s1 += tanh_fast(c[nt][2] + fb0) * av0 + tanh_fast(c[nt][3] + fb1) * av1;
    }
#pragma unroll
    for (int o = 1; o < 4; o <<= 1) {
        s0 += __shfl_xor_sync(0xffffffffu, s0, o);
        s1 += __shfl_xor_sync(0xffffffffu, s1, o);
    }
    if (tig == 0) {
        float c0 = (pr0 < NP) ? s0 : 0.f;
        float c1 = (pr1 < NP) ? s1 : 0.f;
        int mA = (int)(pr0 / NN), mB = (int)(pr1 / NN);
        float add0 = ((mA == m0) ? c0 : 0.f) + ((mB == m0) ? c1 : 0.f);
        float add1 = ((mA != m0) ? c0 : 0.f) + ((mB != m0) ? c1 : 0.f);
        if (add0 != 0.f) atomicAdd(&sLog[0], add0);
        if (add1 != 0.f) atomicAdd(&sLog[1], add1);
    }
    __syncthreads();
    if (tid == 0) {
        if (sLog[0] != 0.f) atomicAdd(&g_logits[m0], sLog[0]);
        if (m0 + 1 < M3 && sLog[1] != 0.f) atomicAdd(&g_logits[m0 + 1], sLog[1]);
    }
}

// ---------------------------------------------------------------------------
// Kernel 4: beta = softmax(logits / N)
// ---------------------------------------------------------------------------
__global__ void beta_kernel() {
    if (threadIdx.x == 0) {
        float l0 = g_logits[0] / (float)NN;
        float l1 = g_logits[1] / (float)NN;
        float l2 = g_logits[2] / (float)NN;
        float mx = fmaxf(l0, fmaxf(l1, l2));
        float e0 = expf(l0 - mx), e1 = expf(l1 - mx), e2 = expf(l2 - mx);
        float s = e0 + e1 + e2;
        g_beta[0] = e0 / s; g_beta[1] = e1 / s; g_beta[2] = e2 / s;
    }
}

// ---------------------------------------------------------------------------
// Kernel 5: z[n][h] = sum_m beta[m] * h[m][n][h]   (fp32 h)
// ---------------------------------------------------------------------------
__global__ __launch_bounds__(256) void z_kernel(float* __restrict__ out) {
    size_t i = (size_t)blockIdx.x * blockDim.x + threadIdx.x;
    size_t tot = (size_t)NN * DH / 4;
    if (i >= tot) return;
    float b0 = g_beta[0], b1 = g_beta[1], b2 = g_beta[2];
    float4 h0 = ((const float4*)(g_h + (size_t)0 * NN * DH))[i];
    float4 h1 = ((const float4*)(g_h + (size_t)1 * NN * DH))[i];
    float4 h2 = ((const float4*)(g_h + (size_t)2 * NN * DH))[i];
    float4 r;
    r.x = b0 * h0.x + b1 * h1.x + b2 * h2.x;
    r.y = b0 * h0.y + b1 * h1.y + b2 * h2.y;
    r.z = b0 * h0.z + b1 * h1.z + b2 * h2.z;
    r.w = b0 * h0.w + b1 * h1.w + b2 * h2.w;
    ((float4*)out)[i] = r;
}

// ---------------------------------------------------------------------------
extern "C" void kernel_launch(void* const* d_in, const int* in_sizes, int n_in,
                              void* d_out, int out_size) {
    const float* feats   = (const float*)d_in[0];
    const int*   src     = (const int*)  d_in[1];
    const int*   dst     = (const int*)  d_in[2];
    const float* W       = (const float*)d_in[3];
    const float* b       = (const float*)d_in[4];
    const float* prelu_a = (const float*)d_in[5];
    const float* fc_W    = (const float*)d_in[6];
    const float* fc_b    = (const float*)d_in[7];
    const float* attn    = (const float*)d_in[8];
    float* out = (float*)d_out;

    // fork a side stream for the CSR chain (capture-legal event fork/join).
    cudaStream_t s2;
    cudaStreamCreateWithFlags(&s2, cudaStreamNonBlocking);
    cudaEvent_t evFork, evJoin;
    cudaEventCreateWithFlags(&evFork, cudaEventDisableTiming);
    cudaEventCreateWithFlags(&evJoin, cudaEventDisableTiming);

    zero_kernel<<<(NP + 255) / 256, 256>>>();
    cudaEventRecord(evFork, 0);
    cudaStreamWaitEvent(s2, evFork, 0);

    // side chain (s2): hist -> scans -> fill  (depends only on src/dst + zeroed cnt)
    hist_kernel<<<(NET + 255) / 256, 256, 0, s2>>>(dst);
    scan1_kernel<<<SCAN_NBLK, 256, 0, s2>>>();
    scan2_kernel<<<1, 32, 0, s2>>>();
    scan3_kernel<<<SCAN_NBLK, 256, 0, s2>>>();
    fill_kernel<<<(NET + 255) / 256, 256, 0, s2>>>(src, dst);
    cudaEventRecord(evJoin, s2);

    // main chain: proj (overlaps with side chain)
    {
        dim3 grid((NN + 63) / 64, M3);
        proj_mma_kernel<<<grid, 128>>>(feats, W);
    }
    cudaStreamWaitEvent(0, evJoin, 0);

    {
        long long threads = (long long)NP * 8;
        aggregate_kernel<<<(int)((threads + 255) / 256), 256>>>(b, prelu_a);
    }
    finalize_mma<<<(NP + 63) / 64, 128>>>(fc_W, fc_b, attn);
    beta_kernel<<<1, 32>>>();
    {
        size_t tot = (size_t)NN * DH / 4;
        z_kernel<<<(int)((tot + 255) / 256), 256>>>(out);
    }
    // handles intentionally not destroyed: destroying capture-referenced
    // events/streams mid-capture is UB; per-call host-handle leak is bounded
    // (kernel_launch runs only for correctness + capture).
}

// round 12
// speedup vs baseline: 2.2788x; 1.0612x over previous
#include <cuda_runtime.h>
#include <cuda_fp16.h>
#include <math.h>

#define NN   100000
#define M3   3
#define DIN  128
#define DH   64
#define NE   1600000
#define NP   300000                     // M3*NN rows
#define NET  4800000                    // M3*NE edges
#define SCAN_CHUNK 2048
#define SCAN_NBLK  147                  // ceil(NP/2048)

// ---- scratch (static device allocations; no cudaMalloc allowed) ----
__device__ __half g_projh[(size_t)NP * DH];      // [p][h] fp16
__device__ __half g_hh [(size_t)NP * DH];        // post-prelu h (fp16)
__device__ int   g_cnt [NP];
__device__ int   g_rowStart[NP];
__device__ int   g_cursor[NP];
__device__ int   g_eidx[NET];
__device__ int   g_blockSums[SCAN_NBLK];
__device__ int   g_blockOff [SCAN_NBLK];
__device__ float g_logits[M3];
__device__ float g_beta[M3];

__device__ __forceinline__ float tanh_fast(float x) {
    float y;
    asm("tanh.approx.f32 %0, %1;" : "=f"(y) : "f"(x));
    return y;
}

// ---------------------------------------------------------------------------
// Kernel 0: zero counters + logits
// ---------------------------------------------------------------------------
__global__ void zero_kernel() {
    int i = blockIdx.x * blockDim.x + threadIdx.x;
    if (i < NP) g_cnt[i] = 0;
    if (i < M3) g_logits[i] = 0.f;
}

// ---------------------------------------------------------------------------
// Kernel 1: proj via fp16 MMA (fp32 accum, fp16 out). 4 warps, 64x64 tile.
// ---------------------------------------------------------------------------
__global__ __launch_bounds__(128) void proj_mma_kernel(const float* __restrict__ feats,
                                                       const float* __restrict__ W) {
    __shared__ __align__(16) __half sA[64 * 136];
    __shared__ __align__(16) __half sW[128 * 72];
    const int m  = blockIdx.y;
    const int n0 = blockIdx.x * 64;
    const int tid = threadIdx.x;
    const int wid = tid >> 5, lane = tid & 31;
    const float* fbase = feats + (size_t)m * NN * DIN;
    const float* wbase = W + (size_t)m * DIN * DH;

    for (int i = tid; i < 64 * 64; i += 128) {
        int r = i >> 6, c2 = i & 63;
        float2 v = make_float2(0.f, 0.f);
        if (n0 + r < NN) v = *(const float2*)&fbase[(size_t)(n0 + r) * DIN + c2 * 2];
        *(__half2*)&sA[r * 136 + c2 * 2] = __floats2half2_rn(v.x, v.y);
    }
    for (int i = tid; i < 128 * 32; i += 128) {
        int r = i >> 5, c2 = i & 31;
        float2 v = *(const float2*)&wbase[(size_t)r * DH + c2 * 2];
        *(__half2*)&sW[r * 72 + c2 * 2] = __floats2half2_rn(v.x, v.y);
    }
    __syncthreads();

    float c[8][4] = {};
    const int rowBase = wid * 16;
    unsigned aBase = (unsigned)__cvta_generic_to_shared(sA);
    unsigned wBase = (unsigned)__cvta_generic_to_shared(sW);

#pragma unroll
    for (int k0 = 0; k0 < 128; k0 += 16) {
        unsigned a0, a1, a2, a3;
        unsigned aAddr = aBase + (unsigned)(((rowBase + (lane & 15)) * 136 + k0 + ((lane >> 4) * 8)) * 2);
        asm volatile("ldmatrix.sync.aligned.m8n8.x4.shared.b16 {%0,%1,%2,%3}, [%4];"
                     : "=r"(a0), "=r"(a1), "=r"(a2), "=r"(a3) : "r"(aAddr));
#pragma unroll
        for (int nt = 0; nt < 8; nt++) {
            unsigned b0, b1;
            unsigned bAddr = wBase + (unsigned)(((k0 + (lane & 15)) * 72 + nt * 8) * 2);
            asm volatile("ldmatrix.sync.aligned.m8n8.x2.trans.shared.b16 {%0,%1}, [%2];"
                         : "=r"(b0), "=r"(b1) : "r"(bAddr));
            asm volatile("mma.sync.aligned.m16n8k16.row.col.f32.f16.f16.f32 "
                         "{%0,%1,%2,%3}, {%4,%5,%6,%7}, {%8,%9}, {%0,%1,%2,%3};"
                         : "+f"(c[nt][0]), "+f"(c[nt][1]), "+f"(c[nt][2]), "+f"(c[nt][3])
                         : "r"(a0), "r"(a1), "r"(a2), "r"(a3), "r"(b0), "r"(b1));
        }
    }

    int groupID = lane >> 2, tig = lane & 3;
    int r0 = n0 + rowBase + groupID;
    int r1 = r0 + 8;
#pragma unroll
    for (int nt = 0; nt < 8; nt++) {
        int col = nt * 8 + tig * 2;
        if (r0 < NN)
            *(__half2*)&g_projh[((size_t)m * NN + r0) * DH + col] = __floats2half2_rn(c[nt][0], c[nt][1]);
        if (r1 < NN)
            *(__half2*)&g_projh[((size_t)m * NN + r1) * DH + col] = __floats2half2_rn(c[nt][2], c[nt][3]);
    }
}

// ---------------------------------------------------------------------------
// Kernel 2a: histogram of dst
// ---------------------------------------------------------------------------
__global__ __launch_bounds__(256) void hist_kernel(const int* __restrict__ dst) {
    int gid = blockIdx.x * blockDim.x + threadIdx.x;
    if (gid >= NET) return;
    int m = gid / NE;
    atomicAdd(&g_cnt[m * NN + dst[gid]], 1);
}

// ---------------------------------------------------------------------------
// Kernel 2b: per-chunk sums
// ---------------------------------------------------------------------------
__global__ __launch_bounds__(256) void scan1_kernel() {
    __shared__ int s[256];
    int tid = threadIdx.x;
    int base = blockIdx.x * SCAN_CHUNK + tid * 8;
    int sum = 0;
#pragma unroll
    for (int j = 0; j < 8; j++) {
        int i = base + j;
        if (i < NP) sum += g_cnt[i];
    }
    s[tid] = sum; __syncthreads();
    for (int off = 128; off; off >>= 1) {
        if (tid < off) s[tid] += s[tid + off];
        __syncthreads();
    }
    if (tid == 0) g_blockSums[blockIdx.x] = s[0];
}

// ---------------------------------------------------------------------------
// Kernel 2c: exclusive scan of 147 chunk sums — parallel Hillis-Steele
// ---------------------------------------------------------------------------
__global__ __launch_bounds__(192) void scan2_kernel() {
    __shared__ int s[192];
    int tid = threadIdx.x;
    int v = (tid < SCAN_NBLK) ? g_blockSums[tid] : 0;
    s[tid] = v; __syncthreads();
    for (int off = 1; off < 192; off <<= 1) {
        int add = (tid >= off) ? s[tid - off] : 0;
        __syncthreads();
        s[tid] += add;
        __syncthreads();
    }
    if (tid < SCAN_NBLK) g_blockOff[tid] = s[tid] - v;   // exclusive
}

// ---------------------------------------------------------------------------
// Kernel 2d: per-chunk exclusive scan -> rowStart, cursor
// ---------------------------------------------------------------------------
__global__ __launch_bounds__(256) void scan3_kernel() {
    __shared__ int s[256];
    int tid = threadIdx.x;
    int base = blockIdx.x * SCAN_CHUNK + tid * 8;
    int cnt8[8];
    int sum = 0;
#pragma unroll
    for (int j = 0; j < 8; j++) {
        int i = base + j;
        cnt8[j] = (i < NP) ? g_cnt[i] : 0;
        sum += cnt8[j];
    }
    s[tid] = sum; __syncthreads();
    for (int off = 1; off < 256; off <<= 1) {
        int add = (tid >= off) ? s[tid - off] : 0;
        __syncthreads();
        s[tid] += add;
        __syncthreads();
    }
    int run = g_blockOff[blockIdx.x] + s[tid] - sum;
#pragma unroll
    for (int j = 0; j < 8; j++) {
        int i = base + j;
        if (i < NP) { g_rowStart[i] = run; g_cursor[i] = run; }
        run += cnt8[j];
    }
}

// ---------------------------------------------------------------------------
// Kernel 2e: fill buckets
// ---------------------------------------------------------------------------
__global__ __launch_bounds__(256) void fill_kernel(const int* __restrict__ src,
                                                   const int* __restrict__ dst) {
    int gid = blockIdx.x * blockDim.x + threadIdx.x;
    if (gid >= NET) return;
    int m = gid / NE;
    int pos = atomicAdd(&g_cursor[m * NN + dst[gid]], 1);
    g_eidx[pos] = m * NN + src[gid];
}

// ---------------------------------------------------------------------------
// Kernel 2f: pull-aggregate: 8 threads/node, uint4 fp16 gathers, fp16 h out.
// ---------------------------------------------------------------------------
__global__ __launch_bounds__(256) void aggregate_kernel(const float* __restrict__ b,
                                                        const float* __restrict__ prelu_a) {
    long long gid = (long long)blockIdx.x * blockDim.x + threadIdx.x;
    long long node8 = gid >> 3;
    if (node8 >= NP) return;
    int p = (int)node8;
    int part = (int)(gid & 7);          // owns cols [part*8, part*8+8)
    int rs = g_rowStart[p];
    int c  = g_cnt[p];

    float acc[8] = {};
    int e = rs, re = rs + c;
    for (; e + 1 < re; e += 2) {
        int i0 = g_eidx[e], i1 = g_eidx[e + 1];
        uint4 r0 = *(const uint4*)&g_projh[(size_t)i0 * DH + part * 8];
        uint4 r1 = *(const uint4*)&g_projh[(size_t)i1 * DH + part * 8];
        float2 t;
        t = __half22float2(*(__half2*)&r0.x); acc[0] += t.x; acc[1] += t.y;
        t = __half22float2(*(__half2*)&r0.y); acc[2] += t.x; acc[3] += t.y;
        t = __half22float2(*(__half2*)&r0.z); acc[4] += t.x; acc[5] += t.y;
        t = __half22float2(*(__half2*)&r0.w); acc[6] += t.x; acc[7] += t.y;
        t = __half22float2(*(__half2*)&r1.x); acc[0] += t.x; acc[1] += t.y;
        t = __half22float2(*(__half2*)&r1.y); acc[2] += t.x; acc[3] += t.y;
        t = __half22float2(*(__half2*)&r1.z); acc[4] += t.x; acc[5] += t.y;
        t = __half22float2(*(__half2*)&r1.w); acc[6] += t.x; acc[7] += t.y;
    }
    if (e < re) {
        int i0 = g_eidx[e];
        uint4 r0 = *(const uint4*)&g_projh[(size_t)i0 * DH + part * 8];
        float2 t;
        t = __half22float2(*(__half2*)&r0.x); acc[0] += t.x; acc[1] += t.y;
        t = __half22float2(*(__half2*)&r0.y); acc[2] += t.x; acc[3] += t.y;
        t = __half22float2(*(__half2*)&r0.z); acc[4] += t.x; acc[5] += t.y;
        t = __half22float2(*(__half2*)&r0.w); acc[6] += t.x; acc[7] += t.y;
    }
    int m = p / NN;
    float inv = 1.0f / (float)max(c, 1);
    float a = prelu_a[m];
    float4 b0 = *(const float4*)&b[m * DH + part * 8];
    float4 b1 = *(const float4*)&b[m * DH + part * 8 + 4];
    float h[8];
    h[0] = acc[0] * inv + b0.x; h[1] = acc[1] * inv + b0.y;
    h[2] = acc[2] * inv + b0.z; h[3] = acc[3] * inv + b0.w;
    h[4] = acc[4] * inv + b1.x; h[5] = acc[5] * inv + b1.y;
    h[6] = acc[6] * inv + b1.z; h[7] = acc[7] * inv + b1.w;
#pragma unroll
    for (int j = 0; j < 8; j++) h[j] = (h[j] > 0.f) ? h[j] : a * h[j];
    __half2 ph[4];
    ph[0] = __floats2half2_rn(h[0], h[1]);
    ph[1] = __floats2half2_rn(h[2], h[3]);
    ph[2] = __floats2half2_rn(h[4], h[5]);
    ph[3] = __floats2half2_rn(h[6], h[7]);
    *(uint4*)&g_hh[(size_t)p * DH + part * 8] = *(uint4*)ph;
}

// ---------------------------------------------------------------------------
// Kernel 3: finalize via fp16 MMA.
// ---------------------------------------------------------------------------
__global__ __launch_bounds__(128) void finalize_mma(const float* __restrict__ fc_W,
                                                    const float* __restrict__ fc_b,
                                                    const float* __restrict__ attn) {
    __shared__ __align__(16) __half sH[64 * 72];
    __shared__ __align__(16) __half sW[64 * 72];
    __shared__ float sLog[2];
    const int tid = threadIdx.x;
    const int wid = tid >> 5, lane = tid & 31;
    const long long p0 = (long long)blockIdx.x * 64;
    const int m0 = (int)(p0 / NN);

    for (int i = tid; i < 64 * 32; i += 128) {
        int r = i >> 5, c2 = i & 31;
        float2 v = *(const float2*)&fc_W[r * DH + c2 * 2];
        *(__half2*)&sW[r * 72 + c2 * 2] = __floats2half2_rn(v.x, v.y);
    }
    for (int i = tid; i < 64 * 8; i += 128) {
        int r = i >> 3, c4 = i & 7;
        long long p = p0 + r;
        uint4 v = make_uint4(0, 0, 0, 0);
        if (p < NP) v = *(const uint4*)&g_hh[(size_t)p * DH + c4 * 8];
        *(uint4*)&sH[r * 72 + c4 * 8] = v;
    }
    if (tid < 2) sLog[tid] = 0.f;
    __syncthreads();

    float c[8][4] = {};
    const int rowBase = wid * 16;
    unsigned hBase = (unsigned)__cvta_generic_to_shared(sH);
    unsigned wBase = (unsigned)__cvta_generic_to_shared(sW);

#pragma unroll
    for (int k0 = 0; k0 < 64; k0 += 16) {
        unsigned a0, a1, a2, a3;
        unsigned aAddr = hBase + (unsigned)(((rowBase + (lane & 15)) * 72 + k0 + ((lane >> 4) * 8)) * 2);
        asm volatile("ldmatrix.sync.aligned.m8n8.x4.shared.b16 {%0,%1,%2,%3}, [%4];"
                     : "=r"(a0), "=r"(a1), "=r"(a2), "=r"(a3) : "r"(aAddr));
#pragma unroll
        for (int nt = 0; nt < 8; nt++) {
            unsigned b0, b1;
            unsigned bAddr = wBase + (unsigned)(((k0 + (lane & 15)) * 72 + nt * 8) * 2);
            asm volatile("ldmatrix.sync.aligned.m8n8.x2.trans.shared.b16 {%0,%1}, [%2];"
                         : "=r"(b0), "=r"(b1) : "r"(bAddr));
            asm volatile("mma.sync.aligned.m16n8k16.row.col.f32.f16.f16.f32 "
                         "{%0,%1,%2,%3}, {%4,%5,%6,%7}, {%8,%9}, {%0,%1,%2,%3};"
                         : "+f"(c[nt][0]), "+f"(c[nt][1]), "+f"(c[nt][2]), "+f"(c[nt][3])
                         : "r"(a0), "r"(a1), "r"(a2), "r"(a3), "r"(b0), "r"(b1));
        }
    }

    int groupID = lane >> 2, tig = lane & 3;
    long long pr0 = p0 + rowBase + groupID;
    long long pr1 = pr0 + 8;
    float s0 = 0.f, s1 = 0.f;
#pragma unroll
    for (int nt = 0; nt < 8; nt++) {
        int col = nt * 8 + tig * 2;
        float fb0 = fc_b[col], fb1 = fc_b[col + 1];
        float av0 = attn[col], av1 = attn[col + 1];
        s0 += tanh_fast(c[nt][0] + fb0) * av0 + tanh_fast(c[nt][1] + fb1) * av1;
        s1 += tanh_fast(c[nt][2] + fb0) * av0 + tanh_fast(c[nt][3] + fb1) * av1;
    }
#pragma unroll
    for (int o = 1; o < 4; o <<= 1) {
        s0 += __shfl_xor_sync(0xffffffffu, s0, o);
        s1 += __shfl_xor_sync(0xffffffffu, s1, o);
    }
    if (tig == 0) {
        float c0 = (pr0 < NP) ? s0 : 0.f;
        float c1 = (pr1 < NP) ? s1 : 0.f;
        int mA = (int)(pr0 / NN), mB = (int)(pr1 / NN);
        float add0 = ((mA == m0) ? c0 : 0.f) + ((mB == m0) ? c1 : 0.f);
        float add1 = ((mA != m0) ? c0 : 0.f) + ((mB != m0) ? c1 : 0.f);
        if (add0 != 0.f) atomicAdd(&sLog[0], add0);
        if (add1 != 0.f) atomicAdd(&sLog[1], add1);
    }
    __syncthreads();
    if (tid == 0) {
        if (sLog[0] != 0.f) atomicAdd(&g_logits[m0], sLog[0]);
        if (m0 + 1 < M3 && sLog[1] != 0.f) atomicAdd(&g_logits[m0 + 1], sLog[1]);
    }
}

// ---------------------------------------------------------------------------
// Kernel 4: beta = softmax(logits / N)
// ---------------------------------------------------------------------------
__global__ void beta_kernel() {
    if (threadIdx.x == 0) {
        float l0 = g_logits[0] / (float)NN;
        float l1 = g_logits[1] / (float)NN;
        float l2 = g_logits[2] / (float)NN;
        float mx = fmaxf(l0, fmaxf(l1, l2));
        float e0 = expf(l0 - mx), e1 = expf(l1 - mx), e2 = expf(l2 - mx);
        float s = e0 + e1 + e2;
        g_beta[0] = e0 / s; g_beta[1] = e1 / s; g_beta[2] = e2 / s;
    }
}

// ---------------------------------------------------------------------------
// Kernel 5: z[n][h] = sum_m beta[m] * h[m][n][h]   (fp16 h, fp32 out)
// ---------------------------------------------------------------------------
__global__ __launch_bounds__(256) void z_kernel(float* __restrict__ out) {
    size_t i = (size_t)blockIdx.x * blockDim.x + threadIdx.x;
    size_t tot = (size_t)NN * DH / 8;           // uint4 = 8 halves
    if (i >= tot) return;
    const size_t stride = (size_t)NN * DH / 8;
    float b0 = g_beta[0], b1 = g_beta[1], b2 = g_beta[2];
    uint4 u0 = ((const uint4*)g_hh)[i];
    uint4 u1 = ((const uint4*)g_hh)[i + stride];
    uint4 u2 = ((const uint4*)g_hh)[i + 2 * stride];
    float r[8];
#pragma unroll
    for (int j = 0; j < 4; j++) {
        float2 t0 = __half22float2(((__half2*)&u0)[j]);
        float2 t1 = __half22float2(((__half2*)&u1)[j]);
        float2 t2 = __half22float2(((__half2*)&u2)[j]);
        r[2 * j]     = b0 * t0.x + b1 * t1.x + b2 * t2.x;
        r[2 * j + 1] = b0 * t0.y + b1 * t1.y + b2 * t2.y;
    }
    float4* o = (float4*)out + i * 2;
    o[0] = make_float4(r[0], r[1], r[2], r[3]);
    o[1] = make_float4(r[4], r[5], r[6], r[7]);
}

// ---------------------------------------------------------------------------
extern "C" void kernel_launch(void* const* d_in, const int* in_sizes, int n_in,
                              void* d_out, int out_size) {
    const float* feats   = (const float*)d_in[0];
    const int*   src     = (const int*)  d_in[1];
    const int*   dst     = (const int*)  d_in[2];
    const float* W       = (const float*)d_in[3];
    const float* b       = (const float*)d_in[4];
    const float* prelu_a = (const float*)d_in[5];
    const float* fc_W    = (const float*)d_in[6];
    const float* fc_b    = (const float*)d_in[7];
    const float* attn    = (const float*)d_in[8];
    float* out = (float*)d_out;

    // fork a side stream for the CSR chain (capture-legal event fork/join).
    cudaStream_t s2;
    cudaStreamCreateWithFlags(&s2, cudaStreamNonBlocking);
    cudaEvent_t evFork, evJoin;
    cudaEventCreateWithFlags(&evFork, cudaEventDisableTiming);
    cudaEventCreateWithFlags(&evJoin, cudaEventDisableTiming);

    zero_kernel<<<(NP + 255) / 256, 256>>>();
    cudaEventRecord(evFork, 0);
    cudaStreamWaitEvent(s2, evFork, 0);

    // side chain (s2): hist -> scans -> fill
    hist_kernel<<<(NET + 255) / 256, 256, 0, s2>>>(dst);
    scan1_kernel<<<SCAN_NBLK, 256, 0, s2>>>();
    scan2_kernel<<<1, 192, 0, s2>>>();
    scan3_kernel<<<SCAN_NBLK, 256, 0, s2>>>();
    fill_kernel<<<(NET + 255) / 256, 256, 0, s2>>>(src, dst);
    cudaEventRecord(evJoin, s2);

    // main chain: proj (overlaps with side chain)
    {
        dim3 grid((NN + 63) / 64, M3);
        proj_mma_kernel<<<grid, 128>>>(feats, W);
    }
    cudaStreamWaitEvent(0, evJoin, 0);

    {
        long long threads = (long long)NP * 8;
        aggregate_kernel<<<(int)((threads + 255) / 256), 256>>>(b, prelu_a);
    }
    finalize_mma<<<(NP + 63) / 64, 128>>>(fc_W, fc_b, attn);
    beta_kernel<<<1, 32>>>();
    {
        size_t tot = (size_t)NN * DH / 8;
        z_kernel<<<(int)((tot + 255) / 256), 256>>>(out);
    }
    // handles intentionally not destroyed (bounded per-call host-handle leak;
    // kernel_launch runs only for correctness + capture).
}